// round 2
// baseline (speedup 1.0000x reference)
#include <cuda_runtime.h>
#include <cuda_fp16.h>
#include <math.h>

#define Bn 8
#define Nn 10000
#define Hh 64
#define Ll 4
#define Rr 3
#define Ee 200000
#define FPn 2048
#define ROWS (Nn*Bn)            /* 80000 rows of 64 floats; row m = n*8+b  */
#define LN_EPS 1e-3f

// ---------------- device scratch (static, no runtime allocation) ----------------
__device__ float  g_x0[ROWS*Hh];            // ping (fp32 master)
__device__ float  g_x1[ROWS*Hh];            // pong (fp32 master)
__device__ __half g_xh[ROWS*Hh];            // fp16 shadow of CURRENT x (gather input)
__device__ float  g_agg[Rr*ROWS*Hh];        // per-relation aggregation (fp32)
__device__ float  g_film[Bn*2*Hh];          // [b][0:64]=1+tanh(gamma), [64:128]=beta
__device__ int    g_rowptr[Rr*(Nn+1)];      // CSR row pointers (by dst)
__device__ int    g_cnt[Rr*Nn];             // degree, then fill cursor
__device__ int    g_esrc[Rr*Ee];            // CSR src ids
__device__ float  g_ew[Rr*Ee];              // CSR edge weights

// ---------------- FiLM: gamma/beta per batch --------------------------------
__global__ void film_kernel(const float* __restrict__ fp,
                            const float* __restrict__ W1, const float* __restrict__ b1,
                            const float* __restrict__ W2, const float* __restrict__ b2)
{
    __shared__ float hid[Bn*Hh];
    int t = threadIdx.x;                   // 512 threads
    int b = t >> 6, h = t & 63;
    float a0 = 0.f, a1 = 0.f, a2 = 0.f, a3 = 0.f;   // break the fma chain
    const float* fpb = fp + b*FPn;
    for (int k = 0; k < FPn; k += 4) {
        a0 = fmaf(fpb[k+0], W1[(k+0)*Hh + h], a0);
        a1 = fmaf(fpb[k+1], W1[(k+1)*Hh + h], a1);
        a2 = fmaf(fpb[k+2], W1[(k+2)*Hh + h], a2);
        a3 = fmaf(fpb[k+3], W1[(k+3)*Hh + h], a3);
    }
    hid[t] = fmaxf(b1[h] + (a0 + a1) + (a2 + a3), 0.f);
    __syncthreads();
    for (int o = t; o < Bn*128; o += 512) {
        int bb = o >> 7, j = o & 127;
        float a = b2[j];
        const float* hb = hid + bb*Hh;
        #pragma unroll
        for (int k = 0; k < Hh; k++) a += hb[k] * W2[k*128 + j];
        if (j < 64) g_film[bb*128 + j] = 1.f + tanhf(a);
        else        g_film[bb*128 + j] = a;
    }
}

// ---------------- initial node features -------------------------------------
__global__ void init_x_kernel(const float* __restrict__ ctl, const float* __restrict__ drug,
                              const float* __restrict__ W_se, const float* __restrict__ b_se,
                              const float* __restrict__ cell_emb, const int* __restrict__ cell_idx)
{
    int i = blockIdx.x*blockDim.x + threadIdx.x;
    if (i >= ROWS*Hh) return;
    int h = i & 63;
    int m = i >> 6;
    int b = m & 7;
    int n = m >> 3;
    float w = W_se[h], bs = b_se[h];
    float v1 = ctl[b*Nn + n], v2 = drug[b*Nn + n];
    float xv = fmaxf(fmaf(v1, w, bs), 0.f) + fmaxf(fmaf(v2, w, bs), 0.f);
    xv += cell_emb[cell_idx[b]*Hh + h];
    xv = fmaf(xv, g_film[b*128 + h], g_film[b*128 + 64 + h]);
    g_x0[i] = xv;
    g_xh[i] = __float2half_rn(xv);
}

// ---------------- CSR build ---------------------------------------------------
__global__ void zero_deg_kernel()
{
    int i = blockIdx.x*blockDim.x + threadIdx.x;
    if (i < Rr*Nn) g_cnt[i] = 0;
}

__global__ void hist_kernel(const int* __restrict__ ei)
{
    int i = blockIdx.x*blockDim.x + threadIdx.x;
    if (i >= Rr*Ee) return;
    int r = i / Ee, e = i - r*Ee;
    int dst = ei[(r*2 + 1)*Ee + e];
    atomicAdd(&g_cnt[r*Nn + dst], 1);
}

__global__ void scan_kernel()   // grid = Rr blocks x 1024 threads, shfl-based
{
    int r = blockIdx.x, t = threadIdx.x;
    int lane = t & 31, warp = t >> 5;
    __shared__ int wsum[32];
    int carry = 0;
    if (t == 0) g_rowptr[r*(Nn+1)] = 0;
    for (int base = 0; base < Nn; base += 1024) {
        int idx = base + t;
        int v = (idx < Nn) ? g_cnt[r*Nn + idx] : 0;
        int s = v;
        #pragma unroll
        for (int off = 1; off < 32; off <<= 1) {
            int nbr = __shfl_up_sync(0xffffffffu, s, off);
            if (lane >= off) s += nbr;
        }
        if (lane == 31) wsum[warp] = s;
        __syncthreads();
        if (warp == 0) {
            int w = wsum[lane];
            #pragma unroll
            for (int off = 1; off < 32; off <<= 1) {
                int nbr = __shfl_up_sync(0xffffffffu, w, off);
                if (lane >= off) w += nbr;
            }
            wsum[lane] = w;
        }
        __syncthreads();
        int tot = carry + (warp ? wsum[warp-1] : 0) + s;
        if (idx < Nn) {
            g_rowptr[r*(Nn+1) + idx + 1] = tot;
            g_cnt[r*Nn + idx] = tot - v;    // exclusive prefix = fill cursor
        }
        carry += wsum[31];
        __syncthreads();
    }
}

__global__ void fill_kernel(const int* __restrict__ ei, const float* __restrict__ ew)
{
    int i = blockIdx.x*blockDim.x + threadIdx.x;
    if (i >= Rr*Ee) return;
    int r = i / Ee, e = i - r*Ee;
    int src = ei[(r*2 + 0)*Ee + e];
    int dst = ei[(r*2 + 1)*Ee + e];
    int pos = atomicAdd(&g_cnt[r*Nn + dst], 1);
    g_esrc[r*Ee + pos] = src;
    g_ew  [r*Ee + pos] = ew[r*Ee + e];
}

// ---------------- gather (fp16 reads): agg_r[dst] = sum_e w_e * x[src_e] ------
__device__ __forceinline__ void acc8(float* acc, uint4 v, float w)
{
    const __half2* h = (const __half2*)&v;
    #pragma unroll
    for (int q = 0; q < 4; q++) {
        float2 f = __half22float2(h[q]);
        acc[2*q]   = fmaf(w, f.x, acc[2*q]);
        acc[2*q+1] = fmaf(w, f.y, acc[2*q+1]);
    }
}

__global__ void gather_kernel()  // grid (Nn, Rr) x 64 threads
{
    int dst = blockIdx.x, r = blockIdx.y;
    int t = threadIdx.x;                       // 8 halfs of the 512-half node row
    int start = g_rowptr[r*(Nn+1) + dst];
    int end   = g_rowptr[r*(Nn+1) + dst + 1];
    const uint4* __restrict__ xq = (const uint4*)g_xh;   // 8 halfs per uint4
    const int*   __restrict__ es = g_esrc + r*Ee;
    const float* __restrict__ ws = g_ew   + r*Ee;
    float acc[8];
    #pragma unroll
    for (int q = 0; q < 8; q++) acc[q] = 0.f;
    int j = start;
    for (; j + 1 < end; j += 2) {
        int s0 = es[j],   s1 = es[j+1];
        float w0 = ws[j], w1 = ws[j+1];
        uint4 v0 = xq[s0*64 + t];
        uint4 v1 = xq[s1*64 + t];
        acc8(acc, v0, w0);
        acc8(acc, v1, w1);
    }
    if (j < end) {
        uint4 v0 = xq[es[j]*64 + t];
        acc8(acc, v0, ws[j]);
    }
    float4* out = (float4*)(g_agg + r*(ROWS*Hh) + dst*512);
    out[t*2]   = make_float4(acc[0], acc[1], acc[2], acc[3]);
    out[t*2+1] = make_float4(acc[4], acc[5], acc[6], acc[7]);
}

// ---------------- fused GEMM (K=256, packed f32x2) + LayerNorm + ReLU ---------
__device__ __forceinline__ unsigned long long ffma2(unsigned long long a,
                                                    unsigned long long b,
                                                    unsigned long long c)
{
    unsigned long long d;
    asm("fma.rn.f32x2 %0, %1, %2, %3;" : "=l"(d) : "l"(a), "l"(b), "l"(c));
    return d;
}

__global__ __launch_bounds__(256)
void gemm_ln_kernel(const float* __restrict__ Wself, const float* __restrict__ Wrel,
                    const float* __restrict__ ln_g,  const float* __restrict__ ln_b,
                    int layer)
{
    const float* xin  = (layer & 1) ? g_x1 : g_x0;
    float*       xout = (layer & 1) ? g_x0 : g_x1;

    __shared__ float sIn[64][68];    // [k][row], padded; float4-aligned rows
    __shared__ float sWD[64][128];   // [k][2*col] duplicated: (w,w) pairs

    int tid = threadIdx.x;
    int row0 = blockIdx.x * 64;
    int tc = tid & 15;              // col group: cols 4*tc..4*tc+3
    int tr = tid >> 4;              // row group: rows 4*tr..4*tr+3

    // acc2[p][j]: packed pair (row 4tr+2p, row 4tr+2p+1) for col 4tc+j
    unsigned long long acc2[2][4];
    #pragma unroll
    for (int p = 0; p < 2; p++)
        #pragma unroll
        for (int jx = 0; jx < 4; jx++) acc2[p][jx] = 0ull;

    for (int s = 0; s < 4; s++) {
        const float* src = (s == 0) ? (xin + row0*Hh)
                                    : (g_agg + (s-1)*(ROWS*Hh) + row0*Hh);
        const float* W   = (s == 0) ? (Wself + layer*Hh*Hh)
                                    : (Wrel + (layer*Rr + (s-1))*Hh*Hh);
        for (int i = tid; i < 4096; i += 256) {
            int kk = i >> 6, cc = i & 63;
            float wv = W[i];
            sWD[kk][2*cc]   = wv;
            sWD[kk][2*cc+1] = wv;
        }
        for (int i = tid; i < 4096; i += 256) {
            int rr = i >> 6, kk = i & 63;
            sIn[kk][rr] = src[i];
        }
        __syncthreads();
        #pragma unroll 16
        for (int k = 0; k < 64; k++) {
            // a: rows 4tr..4tr+3 at depth k -> two packed row-pairs (no MOVs)
            ulonglong2 a2 = *(const ulonglong2*)&sIn[k][tr*4];
            // w: duplicated pairs for cols 4tc..4tc+3
            ulonglong2 wA = *(const ulonglong2*)&sWD[k][tc*8];
            ulonglong2 wB = *(const ulonglong2*)&sWD[k][tc*8 + 4];
            acc2[0][0] = ffma2(a2.x, wA.x, acc2[0][0]);
            acc2[0][1] = ffma2(a2.x, wA.y, acc2[0][1]);
            acc2[0][2] = ffma2(a2.x, wB.x, acc2[0][2]);
            acc2[0][3] = ffma2(a2.x, wB.y, acc2[0][3]);
            acc2[1][0] = ffma2(a2.y, wA.x, acc2[1][0]);
            acc2[1][1] = ffma2(a2.y, wA.y, acc2[1][1]);
            acc2[1][2] = ffma2(a2.y, wB.x, acc2[1][2]);
            acc2[1][3] = ffma2(a2.y, wB.y, acc2[1][3]);
        }
        __syncthreads();
    }

    // LayerNorm + ReLU epilogue; also refresh the fp16 shadow for next gather
    float4 gg = *(const float4*)&ln_g[layer*64 + tc*4];
    float4 bb = *(const float4*)&ln_b[layer*64 + tc*4];
    #pragma unroll
    for (int p = 0; p < 2; p++) {
        #pragma unroll
        for (int hhf = 0; hhf < 2; hhf++) {   // lo/hi half of the packed pair
            float v[4];
            #pragma unroll
            for (int jx = 0; jx < 4; jx++) {
                uint2 u = *(uint2*)&acc2[p][jx];
                v[jx] = __uint_as_float(hhf ? u.y : u.x);
            }
            float s1 = v[0] + v[1] + v[2] + v[3];
            float s2 = v[0]*v[0] + v[1]*v[1] + v[2]*v[2] + v[3]*v[3];
            #pragma unroll
            for (int off = 8; off >= 1; off >>= 1) {
                s1 += __shfl_xor_sync(0xffffffffu, s1, off, 16);
                s2 += __shfl_xor_sync(0xffffffffu, s2, off, 16);
            }
            float mu  = s1 * (1.f/64.f);
            float var = s2 * (1.f/64.f) - mu*mu;
            float inv = rsqrtf(var + LN_EPS);
            float4 o;
            o.x = fmaxf(fmaf((v[0]-mu)*inv, gg.x, bb.x), 0.f);
            o.y = fmaxf(fmaf((v[1]-mu)*inv, gg.y, bb.y), 0.f);
            o.z = fmaxf(fmaf((v[2]-mu)*inv, gg.z, bb.z), 0.f);
            o.w = fmaxf(fmaf((v[3]-mu)*inv, gg.w, bb.w), 0.f);
            int row = row0 + tr*4 + 2*p + hhf;
            *(float4*)&xout[row*64 + tc*4] = o;
            __half2 h01 = __floats2half2_rn(o.x, o.y);
            __half2 h23 = __floats2half2_rn(o.z, o.w);
            uint2 hw;
            hw.x = *(unsigned*)&h01;
            hw.y = *(unsigned*)&h23;
            *(uint2*)(g_xh + row*64 + tc*4) = hw;
        }
    }
}

// ---------------- output projection [B,N] ------------------------------------
__global__ void out_kernel(const float* __restrict__ W_out, const float* __restrict__ b_out,
                           float* __restrict__ out)
{
    int gid  = blockIdx.x*blockDim.x + threadIdx.x;
    int warp = gid >> 5;
    int lane = threadIdx.x & 31;
    if (warp >= ROWS) return;
    const float* xr = g_x0 + warp*64;     // after 4 layers x lives in g_x0
    float v = xr[lane] * W_out[lane] + xr[32 + lane] * W_out[32 + lane];
    #pragma unroll
    for (int off = 16; off >= 1; off >>= 1)
        v += __shfl_xor_sync(0xffffffffu, v, off);
    if (lane == 0) {
        int b = warp & 7, n = warp >> 3;
        out[b*Nn + n] = v + b_out[0];
    }
}

// ---------------- launch ------------------------------------------------------
extern "C" void kernel_launch(void* const* d_in, const int* in_sizes, int n_in,
                              void* d_out, int out_size)
{
    const float* ctl      = (const float*)d_in[0];
    const float* drug     = (const float*)d_in[1];
    const float* fp       = (const float*)d_in[2];
    const float* ew       = (const float*)d_in[3];
    const int*   cell_idx = (const int*)  d_in[4];
    const int*   ei       = (const int*)  d_in[5];
    const float* W_se     = (const float*)d_in[6];
    const float* b_se     = (const float*)d_in[7];
    const float* cell_emb = (const float*)d_in[8];
    const float* W_f1     = (const float*)d_in[9];
    const float* b_f1     = (const float*)d_in[10];
    const float* W_f2     = (const float*)d_in[11];
    const float* b_f2     = (const float*)d_in[12];
    const float* Wself    = (const float*)d_in[13];
    const float* Wrel     = (const float*)d_in[14];
    const float* ln_g     = (const float*)d_in[15];
    const float* ln_b     = (const float*)d_in[16];
    const float* W_out    = (const float*)d_in[17];
    const float* b_out    = (const float*)d_in[18];
    float* out = (float*)d_out;

    film_kernel<<<1, 512>>>(fp, W_f1, b_f1, W_f2, b_f2);
    init_x_kernel<<<(ROWS*Hh + 255)/256, 256>>>(ctl, drug, W_se, b_se, cell_emb, cell_idx);

    zero_deg_kernel<<<(Rr*Nn + 255)/256, 256>>>();
    hist_kernel<<<(Rr*Ee + 255)/256, 256>>>(ei);
    scan_kernel<<<Rr, 1024>>>();
    fill_kernel<<<(Rr*Ee + 255)/256, 256>>>(ei, ew);

    for (int l = 0; l < Ll; l++) {
        gather_kernel<<<dim3(Nn, Rr), 64>>>();
        gemm_ln_kernel<<<ROWS/64, 256>>>(Wself, Wrel, ln_g, ln_b, l);
    }

    out_kernel<<<(ROWS*32 + 255)/256, 256>>>(W_out, b_out, out);
}

// round 3
// speedup vs baseline: 1.4398x; 1.4398x over previous
#include <cuda_runtime.h>
#include <cuda_fp16.h>
#include <math.h>

#define Bn 8
#define Nn 10000
#define Hh 64
#define Ll 4
#define Rr 3
#define Ee 200000
#define FPn 2048
#define ROWS (Nn*Bn)            /* 80000 rows of 64 floats; row m = n*8+b  */
#define LN_EPS 1e-3f

// ---------------- device scratch (static, no runtime allocation) ----------------
__device__ float  g_x0[ROWS*Hh];            // ping (fp32 master)
__device__ float  g_x1[ROWS*Hh];            // pong (fp32 master)
__device__ __half g_xh[ROWS*Hh];            // fp16 shadow of CURRENT x (gather input)
__device__ float  g_agg[Rr*ROWS*Hh];        // per-relation aggregation (fp32)
__device__ float  g_film[Bn*2*Hh];          // [b][0:64]=1+tanh(gamma), [64:128]=beta
__device__ int    g_rowptr[Rr*(Nn+1)];      // CSR row pointers (by dst)
__device__ int    g_cnt[Rr*Nn];             // degree, then fill cursor
__device__ int2   g_epk[Rr*Ee];             // CSR packed (src, weight-bits)

// ---------------- FiLM: gamma/beta per batch --------------------------------
__global__ void film_kernel(const float* __restrict__ fp,
                            const float* __restrict__ W1, const float* __restrict__ b1,
                            const float* __restrict__ W2, const float* __restrict__ b2)
{
    __shared__ float hid[Bn*Hh];
    int t = threadIdx.x;                   // 512 threads
    int b = t >> 6, h = t & 63;
    float a0 = 0.f, a1 = 0.f, a2 = 0.f, a3 = 0.f;
    const float* fpb = fp + b*FPn;
    for (int k = 0; k < FPn; k += 4) {
        a0 = fmaf(fpb[k+0], W1[(k+0)*Hh + h], a0);
        a1 = fmaf(fpb[k+1], W1[(k+1)*Hh + h], a1);
        a2 = fmaf(fpb[k+2], W1[(k+2)*Hh + h], a2);
        a3 = fmaf(fpb[k+3], W1[(k+3)*Hh + h], a3);
    }
    hid[t] = fmaxf(b1[h] + (a0 + a1) + (a2 + a3), 0.f);
    __syncthreads();
    for (int o = t; o < Bn*128; o += 512) {
        int bb = o >> 7, j = o & 127;
        float a = b2[j];
        const float* hb = hid + bb*Hh;
        #pragma unroll
        for (int k = 0; k < Hh; k++) a += hb[k] * W2[k*128 + j];
        if (j < 64) g_film[bb*128 + j] = 1.f + tanhf(a);
        else        g_film[bb*128 + j] = a;
    }
}

// ---------------- initial node features -------------------------------------
__global__ void init_x_kernel(const float* __restrict__ ctl, const float* __restrict__ drug,
                              const float* __restrict__ W_se, const float* __restrict__ b_se,
                              const float* __restrict__ cell_emb, const int* __restrict__ cell_idx)
{
    int i = blockIdx.x*blockDim.x + threadIdx.x;
    if (i >= ROWS*Hh) return;
    int h = i & 63;
    int m = i >> 6;
    int b = m & 7;
    int n = m >> 3;
    float w = W_se[h], bs = b_se[h];
    float v1 = ctl[b*Nn + n], v2 = drug[b*Nn + n];
    float xv = fmaxf(fmaf(v1, w, bs), 0.f) + fmaxf(fmaf(v2, w, bs), 0.f);
    xv += cell_emb[cell_idx[b]*Hh + h];
    xv = fmaf(xv, g_film[b*128 + h], g_film[b*128 + 64 + h]);
    g_x0[i] = xv;
    g_xh[i] = __float2half_rn(xv);
}

// ---------------- CSR build ---------------------------------------------------
__global__ void zero_deg_kernel()
{
    int i = blockIdx.x*blockDim.x + threadIdx.x;
    if (i < Rr*Nn) g_cnt[i] = 0;
}

__global__ void hist_kernel(const int* __restrict__ ei)
{
    int i = blockIdx.x*blockDim.x + threadIdx.x;
    if (i >= Rr*Ee) return;
    int r = i / Ee, e = i - r*Ee;
    int dst = ei[(r*2 + 1)*Ee + e];
    atomicAdd(&g_cnt[r*Nn + dst], 1);
}

__global__ void scan_kernel()   // grid = Rr blocks x 1024 threads, shfl-based
{
    int r = blockIdx.x, t = threadIdx.x;
    int lane = t & 31, warp = t >> 5;
    __shared__ int wsum[32];
    int carry = 0;
    if (t == 0) g_rowptr[r*(Nn+1)] = 0;
    for (int base = 0; base < Nn; base += 1024) {
        int idx = base + t;
        int v = (idx < Nn) ? g_cnt[r*Nn + idx] : 0;
        int s = v;
        #pragma unroll
        for (int off = 1; off < 32; off <<= 1) {
            int nbr = __shfl_up_sync(0xffffffffu, s, off);
            if (lane >= off) s += nbr;
        }
        if (lane == 31) wsum[warp] = s;
        __syncthreads();
        if (warp == 0) {
            int w = wsum[lane];
            #pragma unroll
            for (int off = 1; off < 32; off <<= 1) {
                int nbr = __shfl_up_sync(0xffffffffu, w, off);
                if (lane >= off) w += nbr;
            }
            wsum[lane] = w;
        }
        __syncthreads();
        int tot = carry + (warp ? wsum[warp-1] : 0) + s;
        if (idx < Nn) {
            g_rowptr[r*(Nn+1) + idx + 1] = tot;
            g_cnt[r*Nn + idx] = tot - v;    // exclusive prefix = fill cursor
        }
        carry += wsum[31];
        __syncthreads();
    }
}

__global__ void fill_kernel(const int* __restrict__ ei, const float* __restrict__ ew)
{
    int i = blockIdx.x*blockDim.x + threadIdx.x;
    if (i >= Rr*Ee) return;
    int r = i / Ee, e = i - r*Ee;
    int src = ei[(r*2 + 0)*Ee + e];
    int dst = ei[(r*2 + 1)*Ee + e];
    int pos = atomicAdd(&g_cnt[r*Nn + dst], 1);
    g_epk[r*Ee + pos] = make_int2(src, __float_as_int(ew[r*Ee + e]));
}

// ---------------- gather (fp16 reads): agg_r[dst] = sum_e w_e * x[src_e] ------
// 128 threads/block: thread t owns 4 halfs (8B) of the 1024B node row.
__device__ __forceinline__ void acc4(float* a, uint2 v, float w)
{
    float2 f0 = __half22float2(*(__half2*)&v.x);
    float2 f1 = __half22float2(*(__half2*)&v.y);
    a[0] = fmaf(w, f0.x, a[0]);
    a[1] = fmaf(w, f0.y, a[1]);
    a[2] = fmaf(w, f1.x, a[2]);
    a[3] = fmaf(w, f1.y, a[3]);
}

__global__ void gather_kernel()  // grid (Nn, Rr) x 128 threads
{
    int dst = blockIdx.x, r = blockIdx.y;
    int t = threadIdx.x;
    int start = g_rowptr[r*(Nn+1) + dst];
    int end   = g_rowptr[r*(Nn+1) + dst + 1];
    const uint2* __restrict__ xq = (const uint2*)g_xh;   // 128 uint2 per node row
    const int2*  __restrict__ ep = g_epk + r*Ee;
    float a[4] = {0.f, 0.f, 0.f, 0.f};
    int j = start;
    for (; j + 4 <= end; j += 4) {                      // 4-deep MLP
        int2 e0 = ep[j], e1 = ep[j+1], e2 = ep[j+2], e3 = ep[j+3];
        uint2 v0 = xq[e0.x*128 + t];
        uint2 v1 = xq[e1.x*128 + t];
        uint2 v2 = xq[e2.x*128 + t];
        uint2 v3 = xq[e3.x*128 + t];
        acc4(a, v0, __int_as_float(e0.y));
        acc4(a, v1, __int_as_float(e1.y));
        acc4(a, v2, __int_as_float(e2.y));
        acc4(a, v3, __int_as_float(e3.y));
    }
    for (; j < end; j++) {
        int2 e0 = ep[j];
        uint2 v0 = xq[e0.x*128 + t];
        acc4(a, v0, __int_as_float(e0.y));
    }
    *(float4*)(g_agg + r*(ROWS*Hh) + dst*512 + t*4) = make_float4(a[0], a[1], a[2], a[3]);
}

// ---------------- fused GEMM (K packed f32x2) + LayerNorm + ReLU --------------
__device__ __forceinline__ unsigned long long ffma2u(unsigned long long a,
                                                     unsigned long long b,
                                                     unsigned long long c)
{
    unsigned long long d;
    asm("fma.rn.f32x2 %0, %1, %2, %3;" : "=l"(d) : "l"(a), "l"(b), "l"(c));
    return d;
}
#define F2U(x) (*(const unsigned long long*)&(x))

__global__ __launch_bounds__(256)
void gemm_ln_kernel(const float* __restrict__ Wself, const float* __restrict__ Wrel,
                    const float* __restrict__ ln_g,  const float* __restrict__ ln_b,
                    int layer)
{
    const float* xin  = (layer & 1) ? g_x1 : g_x0;
    float*       xout = (layer & 1) ? g_x0 : g_x1;

    __shared__ float2 sIn2[64*32];   // [row][kp]: natural row-major input (k-pairs)
    __shared__ float4 sWt4[32*32];   // [kp][c/2]: W transposed to k-pair-major

    int tid = threadIdx.x;
    int row0 = blockIdx.x * 64;
    int tc = tid & 15;              // cols 4*tc..4*tc+3
    int tr = tid >> 4;              // rows 4*tr..4*tr+3

    // acc[i][c]: u64 = (even-k partial, odd-k partial) for row 4tr+i, col 4tc+c
    unsigned long long acc[4][4];
    #pragma unroll
    for (int i = 0; i < 4; i++)
        #pragma unroll
        for (int c = 0; c < 4; c++) acc[i][c] = 0ull;

    for (int s = 0; s < 4; s++) {
        const float* src = (s == 0) ? (xin + row0*Hh)
                                    : (g_agg + (s-1)*(ROWS*Hh) + row0*Hh);
        const float* W   = (s == 0) ? (Wself + layer*Hh*Hh)
                                    : (Wrel + (layer*Rr + (s-1))*Hh*Hh);
        // stage input: straight row-major copy (coalesced, conflict-free)
        {
            const float4* s4 = (const float4*)src;
            float4* d4 = (float4*)sIn2;
            #pragma unroll
            for (int i = tid; i < 1024; i += 256) d4[i] = s4[i];
        }
        // stage W transposed to k-pair-major: sWt2[kp*64 + c] = (W[2kp][c], W[2kp+1][c])
        {
            float2* sWt2 = (float2*)sWt4;
            #pragma unroll
            for (int i = tid; i < 2048; i += 256) {
                int kp = i >> 6, c = i & 63;
                sWt2[i] = make_float2(W[(2*kp)*64 + c], W[(2*kp+1)*64 + c]);
            }
        }
        __syncthreads();
        #pragma unroll 8
        for (int kp = 0; kp < 32; kp++) {
            // a: k-pair u64s for 4 rows (broadcast across the 16 tc lanes)
            float2 a0 = sIn2[(4*tr + 0)*32 + kp];
            float2 a1 = sIn2[(4*tr + 1)*32 + kp];
            float2 a2 = sIn2[(4*tr + 2)*32 + kp];
            float2 a3 = sIn2[(4*tr + 3)*32 + kp];
            // w: k-pair u64s for 4 cols (contiguous float4 x2)
            float4 wA = sWt4[kp*32 + 2*tc];       // cols 4tc, 4tc+1
            float4 wB = sWt4[kp*32 + 2*tc + 1];   // cols 4tc+2, 4tc+3
            unsigned long long w0 = F2U(wA.x), w1 = F2U(wA.z);
            unsigned long long w2 = F2U(wB.x), w3 = F2U(wB.z);
            unsigned long long u0 = F2U(a0), u1 = F2U(a1), u2 = F2U(a2), u3 = F2U(a3);
            acc[0][0] = ffma2u(u0, w0, acc[0][0]);
            acc[0][1] = ffma2u(u0, w1, acc[0][1]);
            acc[0][2] = ffma2u(u0, w2, acc[0][2]);
            acc[0][3] = ffma2u(u0, w3, acc[0][3]);
            acc[1][0] = ffma2u(u1, w0, acc[1][0]);
            acc[1][1] = ffma2u(u1, w1, acc[1][1]);
            acc[1][2] = ffma2u(u1, w2, acc[1][2]);
            acc[1][3] = ffma2u(u1, w3, acc[1][3]);
            acc[2][0] = ffma2u(u2, w0, acc[2][0]);
            acc[2][1] = ffma2u(u2, w1, acc[2][1]);
            acc[2][2] = ffma2u(u2, w2, acc[2][2]);
            acc[2][3] = ffma2u(u2, w3, acc[2][3]);
            acc[3][0] = ffma2u(u3, w0, acc[3][0]);
            acc[3][1] = ffma2u(u3, w1, acc[3][1]);
            acc[3][2] = ffma2u(u3, w2, acc[3][2]);
            acc[3][3] = ffma2u(u3, w3, acc[3][3]);
        }
        __syncthreads();
    }

    // LayerNorm + ReLU epilogue; fold k-pair halves; refresh fp16 shadow
    float4 gg = *(const float4*)&ln_g[layer*64 + tc*4];
    float4 bb = *(const float4*)&ln_b[layer*64 + tc*4];
    #pragma unroll
    for (int i = 0; i < 4; i++) {
        float v[4];
        #pragma unroll
        for (int c = 0; c < 4; c++) {
            float2 p = *(float2*)&acc[i][c];
            v[c] = p.x + p.y;
        }
        float s1 = v[0] + v[1] + v[2] + v[3];
        float s2 = v[0]*v[0] + v[1]*v[1] + v[2]*v[2] + v[3]*v[3];
        #pragma unroll
        for (int off = 8; off >= 1; off >>= 1) {
            s1 += __shfl_xor_sync(0xffffffffu, s1, off, 16);
            s2 += __shfl_xor_sync(0xffffffffu, s2, off, 16);
        }
        float mu  = s1 * (1.f/64.f);
        float var = s2 * (1.f/64.f) - mu*mu;
        float inv = rsqrtf(var + LN_EPS);
        float4 o;
        o.x = fmaxf(fmaf((v[0]-mu)*inv, gg.x, bb.x), 0.f);
        o.y = fmaxf(fmaf((v[1]-mu)*inv, gg.y, bb.y), 0.f);
        o.z = fmaxf(fmaf((v[2]-mu)*inv, gg.z, bb.z), 0.f);
        o.w = fmaxf(fmaf((v[3]-mu)*inv, gg.w, bb.w), 0.f);
        int row = row0 + tr*4 + i;
        *(float4*)&xout[row*64 + tc*4] = o;
        __half2 h01 = __floats2half2_rn(o.x, o.y);
        __half2 h23 = __floats2half2_rn(o.z, o.w);
        uint2 hw;
        hw.x = *(unsigned*)&h01;
        hw.y = *(unsigned*)&h23;
        *(uint2*)(g_xh + row*64 + tc*4) = hw;
    }
}

// ---------------- output projection [B,N] ------------------------------------
__global__ void out_kernel(const float* __restrict__ W_out, const float* __restrict__ b_out,
                           float* __restrict__ out)
{
    int gid  = blockIdx.x*blockDim.x + threadIdx.x;
    int warp = gid >> 5;
    int lane = threadIdx.x & 31;
    if (warp >= ROWS) return;
    const float* xr = g_x0 + warp*64;     // after 4 layers x lives in g_x0
    float v = xr[lane] * W_out[lane] + xr[32 + lane] * W_out[32 + lane];
    #pragma unroll
    for (int off = 16; off >= 1; off >>= 1)
        v += __shfl_xor_sync(0xffffffffu, v, off);
    if (lane == 0) {
        int b = warp & 7, n = warp >> 3;
        out[b*Nn + n] = v + b_out[0];
    }
}

// ---------------- launch ------------------------------------------------------
extern "C" void kernel_launch(void* const* d_in, const int* in_sizes, int n_in,
                              void* d_out, int out_size)
{
    const float* ctl      = (const float*)d_in[0];
    const float* drug     = (const float*)d_in[1];
    const float* fp       = (const float*)d_in[2];
    const float* ew       = (const float*)d_in[3];
    const int*   cell_idx = (const int*)  d_in[4];
    const int*   ei       = (const int*)  d_in[5];
    const float* W_se     = (const float*)d_in[6];
    const float* b_se     = (const float*)d_in[7];
    const float* cell_emb = (const float*)d_in[8];
    const float* W_f1     = (const float*)d_in[9];
    const float* b_f1     = (const float*)d_in[10];
    const float* W_f2     = (const float*)d_in[11];
    const float* b_f2     = (const float*)d_in[12];
    const float* Wself    = (const float*)d_in[13];
    const float* Wrel     = (const float*)d_in[14];
    const float* ln_g     = (const float*)d_in[15];
    const float* ln_b     = (const float*)d_in[16];
    const float* W_out    = (const float*)d_in[17];
    const float* b_out    = (const float*)d_in[18];
    float* out = (float*)d_out;

    film_kernel<<<1, 512>>>(fp, W_f1, b_f1, W_f2, b_f2);
    init_x_kernel<<<(ROWS*Hh + 255)/256, 256>>>(ctl, drug, W_se, b_se, cell_emb, cell_idx);

    zero_deg_kernel<<<(Rr*Nn + 255)/256, 256>>>();
    hist_kernel<<<(Rr*Ee + 255)/256, 256>>>(ei);
    scan_kernel<<<Rr, 1024>>>();
    fill_kernel<<<(Rr*Ee + 255)/256, 256>>>(ei, ew);

    for (int l = 0; l < Ll; l++) {
        gather_kernel<<<dim3(Nn, Rr), 128>>>();
        gemm_ln_kernel<<<ROWS/64, 256>>>(Wself, Wrel, ln_g, ln_b, l);
    }

    out_kernel<<<(ROWS*32 + 255)/256, 256>>>(W_out, b_out, out);
}

// round 7
// speedup vs baseline: 2.0237x; 1.4056x over previous
#include <cuda_runtime.h>
#include <cuda_fp16.h>
#include <math.h>
#include <stdint.h>

#define Bn 8
#define Nn 10000
#define Hh 64
#define Ll 4
#define Rr 3
#define Ee 200000
#define FPn 2048
#define ROWS (Nn*Bn)            /* 80000 rows; row m = node*8 + b */
#define LN_EPS 1e-3f
#define KTOT 256                /* x(64) + 3*agg(64) */

// ---------------- device scratch ----------------
__device__ __half g_xh[ROWS*Hh];            // x (fp16) — single state buffer
__device__ __half g_aggh[Rr*ROWS*Hh];       // per-relation aggregation (fp16)
__device__ uint2  g_bfrag[Ll*16*8*32];      // B in exact mma-fragment order
__device__ float  g_film[Bn*2*Hh];
__device__ int    g_rowptr[Rr*(Nn+1)];
__device__ int    g_cnt[Rr*Nn];
__device__ int2   g_epk[Rr*Ee];

// ---------------- FiLM (parallel: 8 blocks x 256) ----------------
__global__ void film_kernel(const float* __restrict__ fp,
                            const float* __restrict__ W1, const float* __restrict__ b1,
                            const float* __restrict__ W2, const float* __restrict__ b2)
{
    int b = blockIdx.x, t = threadIdx.x;
    int h = t >> 2, kc = t & 3;            // 64 h x 4 k-chunks
    __shared__ float part[256];
    __shared__ float hid[64];
    const float* fpb = fp + b*FPn;
    float a0 = 0.f, a1 = 0.f;
    int k0 = kc*512;
    for (int k = k0; k < k0 + 512; k += 2) {
        a0 = fmaf(fpb[k],   W1[k*Hh + h],     a0);
        a1 = fmaf(fpb[k+1], W1[(k+1)*Hh + h], a1);
    }
    part[t] = a0 + a1;
    __syncthreads();
    if (t < 64) {
        float a = part[4*t] + part[4*t+1] + part[4*t+2] + part[4*t+3] + b1[t];
        hid[t] = fmaxf(a, 0.f);
    }
    __syncthreads();
    if (t < 128) {
        int j = t;
        float a = b2[j];
        #pragma unroll
        for (int k = 0; k < Hh; k++) a += hid[k] * W2[k*128 + j];
        if (j < 64) g_film[b*128 + j] = 1.f + tanhf(a);
        else        g_film[b*128 + j] = a;
    }
}

// ---------------- initial node features (fp16 out) ----------------
__global__ void init_x_kernel(const float* __restrict__ ctl, const float* __restrict__ drug,
                              const float* __restrict__ W_se, const float* __restrict__ b_se,
                              const float* __restrict__ cell_emb, const int* __restrict__ cell_idx)
{
    int i = blockIdx.x*blockDim.x + threadIdx.x;
    if (i >= ROWS*Hh) return;
    int h = i & 63;
    int m = i >> 6;
    int b = m & 7;
    int n = m >> 3;
    float w = W_se[h], bs = b_se[h];
    float v1 = ctl[b*Nn + n], v2 = drug[b*Nn + n];
    float xv = fmaxf(fmaf(v1, w, bs), 0.f) + fmaxf(fmaf(v2, w, bs), 0.f);
    xv += cell_emb[cell_idx[b]*Hh + h];
    xv = fmaf(xv, g_film[b*128 + h], g_film[b*128 + 64 + h]);
    g_xh[i] = __float2half_rn(xv);
}

// ---------------- B-fragment prep: layout for mma.m16n8k16.row.col ----------
// frag[l][kt][nt][lane] = uint2{ half2(W[kb][n],W[kb+1][n]), half2(W[kb+8][n],W[kb+9][n]) }
// kb = (kt&3)*16 + (lane&3)*2, n = nt*8 + lane/4; stream s = kt>>2 picks Wself/Wrel.
__global__ void prep_b_kernel(const float* __restrict__ Wself, const float* __restrict__ Wrel)
{
    int idx = blockIdx.x*blockDim.x + threadIdx.x;
    if (idx >= Ll*16*8*32) return;
    int l    = idx >> 12;
    int kt   = (idx >> 8) & 15;
    int nt   = (idx >> 5) & 7;
    int lane = idx & 31;
    int s  = kt >> 2;
    int kb = (kt & 3)*16 + (lane & 3)*2;
    int n  = nt*8 + (lane >> 2);
    const float* W = (s == 0) ? (Wself + l*4096) : (Wrel + (l*Rr + s-1)*4096);
    __half2 lo = __floats2half2_rn(W[kb*64 + n],     W[(kb+1)*64 + n]);
    __half2 hi = __floats2half2_rn(W[(kb+8)*64 + n], W[(kb+9)*64 + n]);
    uint2 u;
    u.x = *(unsigned*)&lo;
    u.y = *(unsigned*)&hi;
    g_bfrag[idx] = u;
}

// ---------------- CSR build ----------------
__global__ void zero_deg_kernel()
{
    int i = blockIdx.x*blockDim.x + threadIdx.x;
    if (i < Rr*Nn) g_cnt[i] = 0;
}

__global__ void hist_kernel(const int* __restrict__ ei)
{
    int i = blockIdx.x*blockDim.x + threadIdx.x;
    if (i >= Rr*Ee) return;
    int r = i / Ee, e = i - r*Ee;
    int dst = ei[(r*2 + 1)*Ee + e];
    atomicAdd(&g_cnt[r*Nn + dst], 1);
}

__global__ void scan_kernel()   // grid = Rr x 1024, shfl-based
{
    int r = blockIdx.x, t = threadIdx.x;
    int lane = t & 31, warp = t >> 5;
    __shared__ int wsum[32];
    int carry = 0;
    if (t == 0) g_rowptr[r*(Nn+1)] = 0;
    for (int base = 0; base < Nn; base += 1024) {
        int idx = base + t;
        int v = (idx < Nn) ? g_cnt[r*Nn + idx] : 0;
        int s = v;
        #pragma unroll
        for (int off = 1; off < 32; off <<= 1) {
            int nbr = __shfl_up_sync(0xffffffffu, s, off);
            if (lane >= off) s += nbr;
        }
        if (lane == 31) wsum[warp] = s;
        __syncthreads();
        if (warp == 0) {
            int w = wsum[lane];
            #pragma unroll
            for (int off = 1; off < 32; off <<= 1) {
                int nbr = __shfl_up_sync(0xffffffffu, w, off);
                if (lane >= off) w += nbr;
            }
            wsum[lane] = w;
        }
        __syncthreads();
        int tot = carry + (warp ? wsum[warp-1] : 0) + s;
        if (idx < Nn) {
            g_rowptr[r*(Nn+1) + idx + 1] = tot;
            g_cnt[r*Nn + idx] = tot - v;
        }
        carry += wsum[31];
        __syncthreads();
    }
}

__global__ void fill_kernel(const int* __restrict__ ei, const float* __restrict__ ew)
{
    int i = blockIdx.x*blockDim.x + threadIdx.x;
    if (i >= Rr*Ee) return;
    int r = i / Ee, e = i - r*Ee;
    int src = ei[(r*2 + 0)*Ee + e];
    int dst = ei[(r*2 + 1)*Ee + e];
    int pos = atomicAdd(&g_cnt[r*Nn + dst], 1);
    g_epk[r*Ee + pos] = make_int2(src, __float_as_int(ew[r*Ee + e]));
}

// ---------------- gather (fp16 in, fp16 out) ----------------
__device__ __forceinline__ void acc4(float* a, uint2 v, float w)
{
    float2 f0 = __half22float2(*(__half2*)&v.x);
    float2 f1 = __half22float2(*(__half2*)&v.y);
    a[0] = fmaf(w, f0.x, a[0]);
    a[1] = fmaf(w, f0.y, a[1]);
    a[2] = fmaf(w, f1.x, a[2]);
    a[3] = fmaf(w, f1.y, a[3]);
}

__global__ void gather_kernel()  // grid (Nn, Rr) x 128
{
    int dst = blockIdx.x, r = blockIdx.y;
    int t = threadIdx.x;
    int start = g_rowptr[r*(Nn+1) + dst];
    int end   = g_rowptr[r*(Nn+1) + dst + 1];
    const uint2* __restrict__ xq = (const uint2*)g_xh;
    const int2*  __restrict__ ep = g_epk + r*Ee;
    float a[4] = {0.f, 0.f, 0.f, 0.f};
    int j = start;
    for (; j + 4 <= end; j += 4) {
        int2 e0 = ep[j], e1 = ep[j+1], e2 = ep[j+2], e3 = ep[j+3];
        uint2 v0 = xq[e0.x*128 + t];
        uint2 v1 = xq[e1.x*128 + t];
        uint2 v2 = xq[e2.x*128 + t];
        uint2 v3 = xq[e3.x*128 + t];
        acc4(a, v0, __int_as_float(e0.y));
        acc4(a, v1, __int_as_float(e1.y));
        acc4(a, v2, __int_as_float(e2.y));
        acc4(a, v3, __int_as_float(e3.y));
    }
    for (; j < end; j++) {
        int2 e0 = ep[j];
        uint2 v0 = xq[e0.x*128 + t];
        acc4(a, v0, __int_as_float(e0.y));
    }
    __half2 h01 = __floats2half2_rn(a[0], a[1]);
    __half2 h23 = __floats2half2_rn(a[2], a[3]);
    uint2 hw;
    hw.x = *(unsigned*)&h01;
    hw.y = *(unsigned*)&h23;
    *(uint2*)(g_aggh + r*(ROWS*Hh) + dst*512 + t*4) = hw;
}

// ---------------- HMMA GEMM (mma.sync m16n8k16) + LayerNorm + ReLU ----------
// Block: 256 threads (8 warps), tile 128 rows. Warp w owns rows m0..m0+15.
__global__ __launch_bounds__(256)
void gemm_mma_kernel(const float* __restrict__ ln_g, const float* __restrict__ ln_b, int layer)
{
    __shared__ uint2 sB[16*8*32];     // 32KB: B fragments for all kt,nt
    __shared__ float sLN[128];        // gamma | beta

    int tid = threadIdx.x;
    int wid = tid >> 5, lane = tid & 31;
    int qr = lane >> 2, qc = lane & 3;

    // stage B fragments (32KB = 2048 uint4) + LN params
    {
        const uint4* src = (const uint4*)(g_bfrag + layer*(16*8*32));
        uint4* d = (uint4*)sB;
        #pragma unroll
        for (int i = tid; i < 2048; i += 256) d[i] = src[i];
        if (tid < 64)        sLN[tid]      = ln_g[layer*64 + tid];
        else if (tid < 128)  sLN[tid]      = ln_b[layer*64 + tid - 64];
    }
    __syncthreads();

    int m0   = blockIdx.x*128 + wid*16;
    int rowA = m0 + qr;

    float c[8][4];
    #pragma unroll
    for (int nt = 0; nt < 8; nt++)
        #pragma unroll
        for (int i = 0; i < 4; i++) c[nt][i] = 0.f;

    #pragma unroll
    for (int kt = 0; kt < 16; kt++) {
        int s  = kt >> 2;
        const __half* A = (s == 0) ? g_xh : (g_aggh + (s-1)*(ROWS*Hh));
        int kk = (kt & 3)*16 + qc*2;
        uint32_t a0 = *(const uint32_t*)(A + rowA*64 + kk);
        uint32_t a1 = *(const uint32_t*)(A + (rowA+8)*64 + kk);
        uint32_t a2 = *(const uint32_t*)(A + rowA*64 + kk + 8);
        uint32_t a3 = *(const uint32_t*)(A + (rowA+8)*64 + kk + 8);
        #pragma unroll
        for (int nt = 0; nt < 8; nt++) {
            uint2 b = sB[(kt*8 + nt)*32 + lane];
            asm volatile(
                "mma.sync.aligned.m16n8k16.row.col.f32.f16.f16.f32 "
                "{%0,%1,%2,%3}, {%4,%5,%6,%7}, {%8,%9}, {%0,%1,%2,%3};"
                : "+f"(c[nt][0]), "+f"(c[nt][1]), "+f"(c[nt][2]), "+f"(c[nt][3])
                : "r"(a0), "r"(a1), "r"(a2), "r"(a3), "r"(b.x), "r"(b.y));
        }
    }

    // LayerNorm + ReLU per row-half; row sums live in the 4 qc lanes of a quad
    #pragma unroll
    for (int h = 0; h < 2; h++) {
        int row = rowA + h*8;
        float sum = 0.f, sq = 0.f;
        #pragma unroll
        for (int nt = 0; nt < 8; nt++) {
            float v0 = c[nt][2*h], v1 = c[nt][2*h + 1];
            sum += v0 + v1;
            sq   = fmaf(v0, v0, fmaf(v1, v1, sq));
        }
        sum += __shfl_xor_sync(0xffffffffu, sum, 1);
        sq  += __shfl_xor_sync(0xffffffffu, sq, 1);
        sum += __shfl_xor_sync(0xffffffffu, sum, 2);
        sq  += __shfl_xor_sync(0xffffffffu, sq, 2);
        float mu  = sum * (1.f/64.f);
        float var = sq  * (1.f/64.f) - mu*mu;
        float inv = rsqrtf(var + LN_EPS);
        #pragma unroll
        for (int nt = 0; nt < 8; nt++) {
            int col = nt*8 + qc*2;
            float o0 = fmaxf(fmaf((c[nt][2*h]  -mu)*inv, sLN[col],   sLN[64+col]),   0.f);
            float o1 = fmaxf(fmaf((c[nt][2*h+1]-mu)*inv, sLN[col+1], sLN[64+col+1]), 0.f);
            __half2 hv = __floats2half2_rn(o0, o1);
            *(unsigned*)(g_xh + row*64 + col) = *(unsigned*)&hv;
        }
    }
}

// ---------------- output projection ----------------
__global__ void out_kernel(const float* __restrict__ W_out, const float* __restrict__ b_out,
                           float* __restrict__ out)
{
    int gid  = blockIdx.x*blockDim.x + threadIdx.x;
    int warp = gid >> 5;
    int lane = threadIdx.x & 31;
    if (warp >= ROWS) return;
    const __half2* xr = (const __half2*)(g_xh + warp*64);
    float2 f = __half22float2(xr[lane]);
    float v = f.x * W_out[2*lane] + f.y * W_out[2*lane + 1];
    #pragma unroll
    for (int off = 16; off >= 1; off >>= 1)
        v += __shfl_xor_sync(0xffffffffu, v, off);
    if (lane == 0) {
        int b = warp & 7, n = warp >> 3;
        out[b*Nn + n] = v + b_out[0];
    }
}

// ---------------- launch ----------------
extern "C" void kernel_launch(void* const* d_in, const int* in_sizes, int n_in,
                              void* d_out, int out_size)
{
    const float* ctl      = (const float*)d_in[0];
    const float* drug     = (const float*)d_in[1];
    const float* fp       = (const float*)d_in[2];
    const float* ew       = (const float*)d_in[3];
    const int*   cell_idx = (const int*)  d_in[4];
    const int*   ei       = (const int*)  d_in[5];
    const float* W_se     = (const float*)d_in[6];
    const float* b_se     = (const float*)d_in[7];
    const float* cell_emb = (const float*)d_in[8];
    const float* W_f1     = (const float*)d_in[9];
    const float* b_f1     = (const float*)d_in[10];
    const float* W_f2     = (const float*)d_in[11];
    const float* b_f2     = (const float*)d_in[12];
    const float* Wself    = (const float*)d_in[13];
    const float* Wrel     = (const float*)d_in[14];
    const float* ln_g     = (const float*)d_in[15];
    const float* ln_b     = (const float*)d_in[16];
    const float* W_out    = (const float*)d_in[17];
    const float* b_out    = (const float*)d_in[18];
    float* out = (float*)d_out;

    film_kernel<<<Bn, 256>>>(fp, W_f1, b_f1, W_f2, b_f2);
    init_x_kernel<<<(ROWS*Hh + 255)/256, 256>>>(ctl, drug, W_se, b_se, cell_emb, cell_idx);
    prep_b_kernel<<<(Ll*16*8*32 + 255)/256, 256>>>(Wself, Wrel);

    zero_deg_kernel<<<(Rr*Nn + 255)/256, 256>>>();
    hist_kernel<<<(Rr*Ee + 255)/256, 256>>>(ei);
    scan_kernel<<<Rr, 1024>>>();
    fill_kernel<<<(Rr*Ee + 255)/256, 256>>>(ei, ew);

    for (int l = 0; l < Ll; l++) {
        gather_kernel<<<dim3(Nn, Rr), 128>>>();
        gemm_mma_kernel<<<ROWS/128, 256>>>(ln_g, ln_b, l);
    }

    out_kernel<<<(ROWS*32 + 255)/256, 256>>>(W_out, b_out, out);
}

// round 8
// speedup vs baseline: 2.4166x; 1.1942x over previous
#include <cuda_runtime.h>
#include <cuda_fp16.h>
#include <math.h>
#include <stdint.h>

#define Bn 8
#define Nn 10000
#define Hh 64
#define Ll 4
#define Rr 3
#define Ee 200000
#define FPn 2048
#define ROWS (Nn*Bn)            /* 80000 rows; row m = node*8 + b */
#define LN_EPS 1e-3f

// ---------------- device scratch ----------------
__device__ __half g_xh[ROWS*Hh];            // x (fp16) — single state buffer
__device__ __half g_aggh[Rr*ROWS*Hh];       // per-relation aggregation (fp16)
__device__ uint2  g_bfrag[Ll*16*8*32];      // B in exact mma-fragment order
__device__ float  g_film[Bn*2*Hh];
__device__ int    g_rowptr[Rr*(Nn+1)];
__device__ int2   g_epk[Rr*Ee];             // CSR packed (src, weight-bits)

// ---------------- single-kernel CSR build: grid Rr x 1024 --------------------
__global__ __launch_bounds__(1024)
void csr_build_kernel(const int* __restrict__ ei, const float* __restrict__ ew)
{
    __shared__ int sh[Nn];       // histogram -> cursor (40000 B)
    __shared__ int wsum[32];
    int r = blockIdx.x, t = threadIdx.x;
    int lane = t & 31, warp = t >> 5;

    // zero
    for (int i = t; i < Nn; i += 1024) sh[i] = 0;
    __syncthreads();

    // histogram over dst
    const int* dstp = ei + (r*2 + 1)*Ee;
    for (int e = t; e < Ee; e += 1024) atomicAdd(&sh[dstp[e]], 1);
    __syncthreads();

    // exclusive scan: rowptr to global, cursor in smem
    int carry = 0;
    if (t == 0) g_rowptr[r*(Nn+1)] = 0;
    for (int base = 0; base < Nn; base += 1024) {
        int idx = base + t;
        int v = (idx < Nn) ? sh[idx] : 0;
        int s = v;
        #pragma unroll
        for (int off = 1; off < 32; off <<= 1) {
            int nbr = __shfl_up_sync(0xffffffffu, s, off);
            if (lane >= off) s += nbr;
        }
        if (lane == 31) wsum[warp] = s;
        __syncthreads();
        if (warp == 0) {
            int w = wsum[lane];
            #pragma unroll
            for (int off = 1; off < 32; off <<= 1) {
                int nbr = __shfl_up_sync(0xffffffffu, w, off);
                if (lane >= off) w += nbr;
            }
            wsum[lane] = w;
        }
        __syncthreads();
        int tot = carry + (warp ? wsum[warp-1] : 0) + s;
        if (idx < Nn) {
            g_rowptr[r*(Nn+1) + idx + 1] = tot;
            sh[idx] = tot - v;               // exclusive prefix = fill cursor
        }
        carry += wsum[31];
        __syncthreads();                     // protect wsum before next round
    }

    // fill
    const int* srcp = ei + (r*2)*Ee;
    const float* wp = ew + r*Ee;
    for (int e = t; e < Ee; e += 1024) {
        int dst = dstp[e];
        int pos = atomicAdd(&sh[dst], 1);
        g_epk[r*Ee + pos] = make_int2(srcp[e], __float_as_int(wp[e]));
    }
}

// ---------------- FiLM (parallel: 8 blocks x 256) ----------------
__global__ void film_kernel(const float* __restrict__ fp,
                            const float* __restrict__ W1, const float* __restrict__ b1,
                            const float* __restrict__ W2, const float* __restrict__ b2)
{
    int b = blockIdx.x, t = threadIdx.x;
    int h = t >> 2, kc = t & 3;            // 64 h x 4 k-chunks
    __shared__ float part[256];
    __shared__ float hid[64];
    const float* fpb = fp + b*FPn;
    float a0 = 0.f, a1 = 0.f;
    int k0 = kc*512;
    for (int k = k0; k < k0 + 512; k += 2) {
        a0 = fmaf(fpb[k],   W1[k*Hh + h],     a0);
        a1 = fmaf(fpb[k+1], W1[(k+1)*Hh + h], a1);
    }
    part[t] = a0 + a1;
    __syncthreads();
    if (t < 64) {
        float a = part[4*t] + part[4*t+1] + part[4*t+2] + part[4*t+3] + b1[t];
        hid[t] = fmaxf(a, 0.f);
    }
    __syncthreads();
    if (t < 128) {
        int j = t;
        float a = b2[j];
        #pragma unroll
        for (int k = 0; k < Hh; k++) a += hid[k] * W2[k*128 + j];
        if (j < 64) g_film[b*128 + j] = 1.f + tanhf(a);
        else        g_film[b*128 + j] = a;
    }
}

// ---------------- initial node features (fp16 out) ----------------
__global__ void init_x_kernel(const float* __restrict__ ctl, const float* __restrict__ drug,
                              const float* __restrict__ W_se, const float* __restrict__ b_se,
                              const float* __restrict__ cell_emb, const int* __restrict__ cell_idx)
{
    int i = blockIdx.x*blockDim.x + threadIdx.x;
    if (i >= ROWS*Hh) return;
    int h = i & 63;
    int m = i >> 6;
    int b = m & 7;
    int n = m >> 3;
    float w = W_se[h], bs = b_se[h];
    float v1 = ctl[b*Nn + n], v2 = drug[b*Nn + n];
    float xv = fmaxf(fmaf(v1, w, bs), 0.f) + fmaxf(fmaf(v2, w, bs), 0.f);
    xv += cell_emb[cell_idx[b]*Hh + h];
    xv = fmaf(xv, g_film[b*128 + h], g_film[b*128 + 64 + h]);
    g_xh[i] = __float2half_rn(xv);
}

// ---------------- B-fragment prep: layout for mma.m16n8k16.row.col ----------
__global__ void prep_b_kernel(const float* __restrict__ Wself, const float* __restrict__ Wrel)
{
    int idx = blockIdx.x*blockDim.x + threadIdx.x;
    if (idx >= Ll*16*8*32) return;
    int l    = idx >> 12;
    int kt   = (idx >> 8) & 15;
    int nt   = (idx >> 5) & 7;
    int lane = idx & 31;
    int s  = kt >> 2;
    int kb = (kt & 3)*16 + (lane & 3)*2;
    int n  = nt*8 + (lane >> 2);
    const float* W = (s == 0) ? (Wself + l*4096) : (Wrel + (l*Rr + s-1)*4096);
    __half2 lo = __floats2half2_rn(W[kb*64 + n],     W[(kb+1)*64 + n]);
    __half2 hi = __floats2half2_rn(W[(kb+8)*64 + n], W[(kb+9)*64 + n]);
    uint2 u;
    u.x = *(unsigned*)&lo;
    u.y = *(unsigned*)&hi;
    g_bfrag[idx] = u;
}

// ---------------- gather: smem meta staging, 128 thr/CTA --------------------
#define GCH 128
__device__ __forceinline__ void acc4(float* a, uint2 v, float w)
{
    float2 f0 = __half22float2(*(__half2*)&v.x);
    float2 f1 = __half22float2(*(__half2*)&v.y);
    a[0] = fmaf(w, f0.x, a[0]);
    a[1] = fmaf(w, f0.y, a[1]);
    a[2] = fmaf(w, f1.x, a[2]);
    a[3] = fmaf(w, f1.y, a[3]);
}

__global__ void gather_kernel()  // grid (Nn, Rr) x 128
{
    __shared__ int2 sM[GCH];
    int dst = blockIdx.x, r = blockIdx.y;
    int t = threadIdx.x;
    int start = g_rowptr[r*(Nn+1) + dst];
    int end   = g_rowptr[r*(Nn+1) + dst + 1];
    const uint2* __restrict__ xq = (const uint2*)g_xh;
    const int2*  __restrict__ ep = g_epk + r*Ee;
    float a[4] = {0.f, 0.f, 0.f, 0.f};

    for (int base = start; base < end; base += GCH) {
        int n = min(GCH, end - base);
        if (t < n) sM[t] = ep[base + t];
        __syncthreads();
        int j = 0;
        for (; j + 4 <= n; j += 4) {
            int2 e0 = sM[j], e1 = sM[j+1], e2 = sM[j+2], e3 = sM[j+3];
            uint2 v0 = xq[e0.x*128 + t];
            uint2 v1 = xq[e1.x*128 + t];
            uint2 v2 = xq[e2.x*128 + t];
            uint2 v3 = xq[e3.x*128 + t];
            acc4(a, v0, __int_as_float(e0.y));
            acc4(a, v1, __int_as_float(e1.y));
            acc4(a, v2, __int_as_float(e2.y));
            acc4(a, v3, __int_as_float(e3.y));
        }
        for (; j < n; j++) {
            int2 e0 = sM[j];
            uint2 v0 = xq[e0.x*128 + t];
            acc4(a, v0, __int_as_float(e0.y));
        }
        __syncthreads();
    }
    __half2 h01 = __floats2half2_rn(a[0], a[1]);
    __half2 h23 = __floats2half2_rn(a[2], a[3]);
    uint2 hw;
    hw.x = *(unsigned*)&h01;
    hw.y = *(unsigned*)&h23;
    *(uint2*)(g_aggh + r*(ROWS*Hh) + dst*512 + t*4) = hw;
}

// ---------------- HMMA GEMM + LayerNorm + ReLU (+ fused out on final) -------
__global__ __launch_bounds__(256)
void gemm_mma_kernel(const float* __restrict__ ln_g, const float* __restrict__ ln_b,
                     const float* __restrict__ W_out, const float* __restrict__ b_out,
                     float* __restrict__ out, int layer, int final_layer)
{
    __shared__ uint2 sB[16*8*32];     // 32KB: B fragments for all kt,nt
    __shared__ float sLN[194];        // gamma(64) | beta(64) | W_out(64) | b_out

    int tid = threadIdx.x;
    int wid = tid >> 5, lane = tid & 31;
    int qr = lane >> 2, qc = lane & 3;

    // stage B fragments (32KB = 2048 uint4) + LN/out params
    {
        const uint4* src = (const uint4*)(g_bfrag + layer*(16*8*32));
        uint4* d = (uint4*)sB;
        #pragma unroll
        for (int i = tid; i < 2048; i += 256) d[i] = src[i];
        if (tid < 64)        sLN[tid] = ln_g[layer*64 + tid];
        else if (tid < 128)  sLN[tid] = ln_b[layer*64 + tid - 64];
        else if (tid < 192)  sLN[tid] = W_out[tid - 128];
        else if (tid == 192) sLN[192] = b_out[0];
    }
    __syncthreads();

    int m0   = blockIdx.x*128 + wid*16;
    int rowA = m0 + qr;

    float c[8][4];
    #pragma unroll
    for (int nt = 0; nt < 8; nt++)
        #pragma unroll
        for (int i = 0; i < 4; i++) c[nt][i] = 0.f;

    #pragma unroll
    for (int kt = 0; kt < 16; kt++) {
        int s  = kt >> 2;
        const __half* A = (s == 0) ? g_xh : (g_aggh + (s-1)*(ROWS*Hh));
        int kk = (kt & 3)*16 + qc*2;
        uint32_t a0 = *(const uint32_t*)(A + rowA*64 + kk);
        uint32_t a1 = *(const uint32_t*)(A + (rowA+8)*64 + kk);
        uint32_t a2 = *(const uint32_t*)(A + rowA*64 + kk + 8);
        uint32_t a3 = *(const uint32_t*)(A + (rowA+8)*64 + kk + 8);
        #pragma unroll
        for (int nt = 0; nt < 8; nt++) {
            uint2 b = sB[(kt*8 + nt)*32 + lane];
            asm volatile(
                "mma.sync.aligned.m16n8k16.row.col.f32.f16.f16.f32 "
                "{%0,%1,%2,%3}, {%4,%5,%6,%7}, {%8,%9}, {%0,%1,%2,%3};"
                : "+f"(c[nt][0]), "+f"(c[nt][1]), "+f"(c[nt][2]), "+f"(c[nt][3])
                : "r"(a0), "r"(a1), "r"(a2), "r"(a3), "r"(b.x), "r"(b.y));
        }
    }

    // LayerNorm + ReLU per row-half; quad shuffle over qc lanes
    #pragma unroll
    for (int h = 0; h < 2; h++) {
        int row = rowA + h*8;
        float sum = 0.f, sq = 0.f;
        #pragma unroll
        for (int nt = 0; nt < 8; nt++) {
            float v0 = c[nt][2*h], v1 = c[nt][2*h + 1];
            sum += v0 + v1;
            sq   = fmaf(v0, v0, fmaf(v1, v1, sq));
        }
        sum += __shfl_xor_sync(0xffffffffu, sum, 1);
        sq  += __shfl_xor_sync(0xffffffffu, sq, 1);
        sum += __shfl_xor_sync(0xffffffffu, sum, 2);
        sq  += __shfl_xor_sync(0xffffffffu, sq, 2);
        float mu  = sum * (1.f/64.f);
        float var = sq  * (1.f/64.f) - mu*mu;
        float inv = rsqrtf(var + LN_EPS);
        if (!final_layer) {
            #pragma unroll
            for (int nt = 0; nt < 8; nt++) {
                int col = nt*8 + qc*2;
                float o0 = fmaxf(fmaf((c[nt][2*h]  -mu)*inv, sLN[col],   sLN[64+col]),   0.f);
                float o1 = fmaxf(fmaf((c[nt][2*h+1]-mu)*inv, sLN[col+1], sLN[64+col+1]), 0.f);
                __half2 hv = __floats2half2_rn(o0, o1);
                *(unsigned*)(g_xh + row*64 + col) = *(unsigned*)&hv;
            }
        } else {
            float dot = 0.f;
            #pragma unroll
            for (int nt = 0; nt < 8; nt++) {
                int col = nt*8 + qc*2;
                float o0 = fmaxf(fmaf((c[nt][2*h]  -mu)*inv, sLN[col],   sLN[64+col]),   0.f);
                float o1 = fmaxf(fmaf((c[nt][2*h+1]-mu)*inv, sLN[col+1], sLN[64+col+1]), 0.f);
                dot = fmaf(o0, sLN[128+col], fmaf(o1, sLN[128+col+1], dot));
            }
            dot += __shfl_xor_sync(0xffffffffu, dot, 1);
            dot += __shfl_xor_sync(0xffffffffu, dot, 2);
            if (qc == 0) {
                int b = row & 7, n = row >> 3;
                out[b*Nn + n] = dot + sLN[192];
            }
        }
    }
}

// ---------------- launch ----------------
extern "C" void kernel_launch(void* const* d_in, const int* in_sizes, int n_in,
                              void* d_out, int out_size)
{
    const float* ctl      = (const float*)d_in[0];
    const float* drug     = (const float*)d_in[1];
    const float* fp       = (const float*)d_in[2];
    const float* ew       = (const float*)d_in[3];
    const int*   cell_idx = (const int*)  d_in[4];
    const int*   ei       = (const int*)  d_in[5];
    const float* W_se     = (const float*)d_in[6];
    const float* b_se     = (const float*)d_in[7];
    const float* cell_emb = (const float*)d_in[8];
    const float* W_f1     = (const float*)d_in[9];
    const float* b_f1     = (const float*)d_in[10];
    const float* W_f2     = (const float*)d_in[11];
    const float* b_f2     = (const float*)d_in[12];
    const float* Wself    = (const float*)d_in[13];
    const float* Wrel     = (const float*)d_in[14];
    const float* ln_g     = (const float*)d_in[15];
    const float* ln_b     = (const float*)d_in[16];
    const float* W_out    = (const float*)d_in[17];
    const float* b_out    = (const float*)d_in[18];
    float* out = (float*)d_out;

    csr_build_kernel<<<Rr, 1024>>>(ei, ew);                                   // 1
    film_kernel<<<Bn, 256>>>(fp, W_f1, b_f1, W_f2, b_f2);                     // 2
    init_x_kernel<<<(ROWS*Hh + 255)/256, 256>>>(ctl, drug, W_se, b_se,
                                                cell_emb, cell_idx);          // 3
    gather_kernel<<<dim3(Nn, Rr), 128>>>();                                   // 4  <- profiled
    prep_b_kernel<<<(Ll*16*8*32 + 255)/256, 256>>>(Wself, Wrel);              // 5

    for (int l = 0; l < Ll; l++) {
        if (l > 0) gather_kernel<<<dim3(Nn, Rr), 128>>>();
        gemm_mma_kernel<<<ROWS/128, 256>>>(ln_g, ln_b, W_out, b_out, out,
                                           l, (l == Ll-1) ? 1 : 0);
    }
}

// round 9
// speedup vs baseline: 2.8862x; 1.1943x over previous
#include <cuda_runtime.h>
#include <cuda_fp16.h>
#include <math.h>
#include <stdint.h>

#define Bn 8
#define Nn 10000
#define Hh 64
#define Ll 4
#define Rr 3
#define Ee 200000
#define FPn 2048
#define ROWS (Nn*Bn)            /* 80000 rows; row m = node*8 + b */
#define LN_EPS 1e-3f
#define ESEG 8                  /* blocks per relation for hist/fill */
#define ECHUNK (Ee/ESEG)        /* 25000 */

// ---------------- device scratch ----------------
__device__ __half g_xh[ROWS*Hh];            // x (fp16) — single state buffer
__device__ __half g_aggh[Rr*ROWS*Hh];       // per-relation aggregation (fp16)
__device__ uint2  g_bfrag[Ll*16*8*32];      // B in exact mma-fragment order
__device__ float  g_film[Bn*2*Hh];
__device__ int    g_hist[Rr*Nn];            // degree hist (re-zeroed by scan)
__device__ int    g_rowptr[Rr*(Nn+1)];
__device__ int    g_cnt[Rr*Nn];             // atomic fill cursors
__device__ int4   g_epk[Rr*Ee];             // CSR packed (src, 0, wbits, wbits)

// ---------------- packed f32x2 fma ----------------
__device__ __forceinline__ unsigned long long ffma2u(unsigned long long a,
                                                     unsigned long long b,
                                                     unsigned long long c)
{
    unsigned long long d;
    asm("fma.rn.f32x2 %0, %1, %2, %3;" : "=l"(d) : "l"(a), "l"(b), "l"(c));
    return d;
}
__device__ __forceinline__ unsigned long long pack64(float lo, float hi)
{
    unsigned long long u;
    asm("mov.b64 %0, {%1, %2};" : "=l"(u) : "f"(lo), "f"(hi));
    return u;
}

// ---------------- pre-kernel: hist(24) + film(8) + prep_b(16), 1024 thr -----
__global__ __launch_bounds__(1024)
void pre_kernel(const int* __restrict__ ei,
                const float* __restrict__ fp,
                const float* __restrict__ W1, const float* __restrict__ b1,
                const float* __restrict__ W2, const float* __restrict__ b2,
                const float* __restrict__ Wself, const float* __restrict__ Wrel)
{
    __shared__ int   sh[Nn];        // hist blocks
    __shared__ float part[1024];    // film blocks
    __shared__ float hid[64];
    int bk = blockIdx.x, t = threadIdx.x;

    if (bk < Rr*ESEG) {
        // ---- histogram (private smem, merged to global) ----
        int r = bk / ESEG, seg = bk % ESEG;
        for (int i = t; i < Nn; i += 1024) sh[i] = 0;
        __syncthreads();
        const int* dstp = ei + (r*2 + 1)*Ee + seg*ECHUNK;
        for (int e = t; e < ECHUNK; e += 1024) atomicAdd(&sh[dstp[e]], 1);
        __syncthreads();
        for (int i = t; i < Nn; i += 1024) {
            int v = sh[i];
            if (v) atomicAdd(&g_hist[r*Nn + i], v);
        }
    } else if (bk < Rr*ESEG + Bn) {
        // ---- FiLM for batch b ----
        int b = bk - Rr*ESEG;
        int h = t >> 4, kc = t & 15;           // 64 h x 16 chunks of 128
        const float* fpb = fp + b*FPn;
        float a0 = 0.f, a1 = 0.f;
        int k0 = kc*128;
        for (int k = k0; k < k0 + 128; k += 2) {
            a0 = fmaf(fpb[k],   W1[k*Hh + h],     a0);
            a1 = fmaf(fpb[k+1], W1[(k+1)*Hh + h], a1);
        }
        part[t] = a0 + a1;
        __syncthreads();
        if (t < 64) {
            float a = b1[t];
            #pragma unroll
            for (int i = 0; i < 16; i++) a += part[t*16 + i];
            hid[t] = fmaxf(a, 0.f);
        }
        __syncthreads();
        if (t < 128) {
            int j = t;
            float a = b2[j];
            #pragma unroll
            for (int k = 0; k < Hh; k++) a += hid[k] * W2[k*128 + j];
            if (j < 64) g_film[b*128 + j] = 1.f + tanhf(a);
            else        g_film[b*128 + j] = a;
        }
    } else {
        // ---- B-fragment prep for mma.m16n8k16.row.col ----
        int idx = (bk - Rr*ESEG - Bn)*1024 + t;
        if (idx < Ll*16*8*32) {
            int l    = idx >> 12;
            int kt   = (idx >> 8) & 15;
            int nt   = (idx >> 5) & 7;
            int lane = idx & 31;
            int s  = kt >> 2;
            int kb = (kt & 3)*16 + (lane & 3)*2;
            int n  = nt*8 + (lane >> 2);
            const float* W = (s == 0) ? (Wself + l*4096) : (Wrel + (l*Rr + s-1)*4096);
            __half2 lo = __floats2half2_rn(W[kb*64 + n],     W[(kb+1)*64 + n]);
            __half2 hi = __floats2half2_rn(W[(kb+8)*64 + n], W[(kb+9)*64 + n]);
            uint2 u;
            u.x = *(unsigned*)&lo;
            u.y = *(unsigned*)&hi;
            g_bfrag[idx] = u;
        }
    }
}

// ---------------- scan: rowptr + cursors; re-zeros g_hist for replay --------
__global__ __launch_bounds__(1024)
void scan_kernel()   // grid = Rr x 1024
{
    __shared__ int wsum[32];
    int r = blockIdx.x, t = threadIdx.x;
    int lane = t & 31, warp = t >> 5;
    int carry = 0;
    if (t == 0) g_rowptr[r*(Nn+1)] = 0;
    for (int base = 0; base < Nn; base += 1024) {
        int idx = base + t;
        int v = (idx < Nn) ? g_hist[r*Nn + idx] : 0;
        int s = v;
        #pragma unroll
        for (int off = 1; off < 32; off <<= 1) {
            int nbr = __shfl_up_sync(0xffffffffu, s, off);
            if (lane >= off) s += nbr;
        }
        if (lane == 31) wsum[warp] = s;
        __syncthreads();
        if (warp == 0) {
            int w = wsum[lane];
            #pragma unroll
            for (int off = 1; off < 32; off <<= 1) {
                int nbr = __shfl_up_sync(0xffffffffu, w, off);
                if (lane >= off) w += nbr;
            }
            wsum[lane] = w;
        }
        __syncthreads();
        int tot = carry + (warp ? wsum[warp-1] : 0) + s;
        if (idx < Nn) {
            g_rowptr[r*(Nn+1) + idx + 1] = tot;
            g_cnt[r*Nn + idx]  = tot - v;    // exclusive prefix = fill cursor
            g_hist[r*Nn + idx] = 0;          // ready for next graph replay
        }
        carry += wsum[31];
        __syncthreads();
    }
}

// ---------------- initial node features (fp16 out) ----------------
__global__ void init_x_kernel(const float* __restrict__ ctl, const float* __restrict__ drug,
                              const float* __restrict__ W_se, const float* __restrict__ b_se,
                              const float* __restrict__ cell_emb, const int* __restrict__ cell_idx)
{
    int i = blockIdx.x*blockDim.x + threadIdx.x;
    if (i >= ROWS*Hh) return;
    int h = i & 63;
    int m = i >> 6;
    int b = m & 7;
    int n = m >> 3;
    float w = W_se[h], bs = b_se[h];
    float v1 = ctl[b*Nn + n], v2 = drug[b*Nn + n];
    float xv = fmaxf(fmaf(v1, w, bs), 0.f) + fmaxf(fmaf(v2, w, bs), 0.f);
    xv += cell_emb[cell_idx[b]*Hh + h];
    xv = fmaf(xv, g_film[b*128 + h], g_film[b*128 + 64 + h]);
    g_xh[i] = __float2half_rn(xv);
}

// ---------------- fill: 24 blocks, global atomic cursors --------------------
__global__ __launch_bounds__(1024)
void fill_kernel(const int* __restrict__ ei, const float* __restrict__ ew)
{
    int bk = blockIdx.x, t = threadIdx.x;
    int r = bk / ESEG, seg = bk % ESEG;
    const int* dstp = ei + (r*2 + 1)*Ee + seg*ECHUNK;
    const int* srcp = ei + (r*2 + 0)*Ee + seg*ECHUNK;
    const float* wp = ew + r*Ee + seg*ECHUNK;
    for (int e = t; e < ECHUNK; e += 1024) {
        int dst = dstp[e];
        int pos = atomicAdd(&g_cnt[r*Nn + dst], 1);
        int wb  = __float_as_int(wp[e]);
        g_epk[r*Ee + pos] = make_int4(srcp[e], 0, wb, wb);
    }
}

// ---------------- gather: 64 thr x uint4, FFMA2, smem meta ------------------
#define GCH 128
__device__ __forceinline__ void macc8(unsigned long long* acc, uint4 v,
                                      unsigned long long w2)
{
    float2 f0 = __half22float2(*(__half2*)&v.x);
    float2 f1 = __half22float2(*(__half2*)&v.y);
    float2 f2 = __half22float2(*(__half2*)&v.z);
    float2 f3 = __half22float2(*(__half2*)&v.w);
    acc[0] = ffma2u(pack64(f0.x, f0.y), w2, acc[0]);
    acc[1] = ffma2u(pack64(f1.x, f1.y), w2, acc[1]);
    acc[2] = ffma2u(pack64(f2.x, f2.y), w2, acc[2]);
    acc[3] = ffma2u(pack64(f3.x, f3.y), w2, acc[3]);
}

__global__ __launch_bounds__(64)
void gather_kernel()  // grid (Nn, Rr) x 64
{
    __shared__ int4 sM[GCH];
    int dst = blockIdx.x, r = blockIdx.y;
    int t = threadIdx.x;                       // owns 8 halfs of the 512-half row
    int start = g_rowptr[r*(Nn+1) + dst];
    int end   = g_rowptr[r*(Nn+1) + dst + 1];
    const uint4* __restrict__ xq = (const uint4*)g_xh;   // 64 uint4 per node row
    const int4*  __restrict__ ep = g_epk + r*Ee;
    unsigned long long acc[4] = {0ull, 0ull, 0ull, 0ull};

    for (int base = start; base < end; base += GCH) {
        int n = min(GCH, end - base);
        if (t < n)       sM[t]      = ep[base + t];
        if (t + 64 < n)  sM[t + 64] = ep[base + t + 64];
        __syncthreads();
        int j = 0;
        for (; j + 4 <= n; j += 4) {
            int4 m0 = sM[j], m1 = sM[j+1], m2 = sM[j+2], m3 = sM[j+3];
            uint4 v0 = xq[m0.x*64 + t];
            uint4 v1 = xq[m1.x*64 + t];
            uint4 v2 = xq[m2.x*64 + t];
            uint4 v3 = xq[m3.x*64 + t];
            macc8(acc, v0, *(unsigned long long*)&m0.z);
            macc8(acc, v1, *(unsigned long long*)&m1.z);
            macc8(acc, v2, *(unsigned long long*)&m2.z);
            macc8(acc, v3, *(unsigned long long*)&m3.z);
        }
        for (; j < n; j++) {
            int4 m0 = sM[j];
            uint4 v0 = xq[m0.x*64 + t];
            macc8(acc, v0, *(unsigned long long*)&m0.z);
        }
        __syncthreads();
    }

    uint4 hw;
    unsigned* hp = (unsigned*)&hw;
    #pragma unroll
    for (int q = 0; q < 4; q++) {
        float2 f = *(float2*)&acc[q];
        __half2 h = __floats2half2_rn(f.x, f.y);
        hp[q] = *(unsigned*)&h;
    }
    ((uint4*)(g_aggh + r*(ROWS*Hh) + dst*512))[t] = hw;
}

// ---------------- HMMA GEMM + LayerNorm + ReLU (+ fused out on final) -------
__global__ __launch_bounds__(256)
void gemm_mma_kernel(const float* __restrict__ ln_g, const float* __restrict__ ln_b,
                     const float* __restrict__ W_out, const float* __restrict__ b_out,
                     float* __restrict__ out, int layer, int final_layer)
{
    __shared__ uint2 sB[16*8*32];     // 32KB: B fragments for all kt,nt
    __shared__ float sLN[194];        // gamma(64) | beta(64) | W_out(64) | b_out

    int tid = threadIdx.x;
    int wid = tid >> 5, lane = tid & 31;
    int qr = lane >> 2, qc = lane & 3;

    {
        const uint4* src = (const uint4*)(g_bfrag + layer*(16*8*32));
        uint4* d = (uint4*)sB;
        #pragma unroll
        for (int i = tid; i < 2048; i += 256) d[i] = src[i];
        if (tid < 64)        sLN[tid] = ln_g[layer*64 + tid];
        else if (tid < 128)  sLN[tid] = ln_b[layer*64 + tid - 64];
        else if (tid < 192)  sLN[tid] = W_out[tid - 128];
        else if (tid == 192) sLN[192] = b_out[0];
    }
    __syncthreads();

    int m0   = blockIdx.x*128 + wid*16;
    int rowA = m0 + qr;

    float c[8][4];
    #pragma unroll
    for (int nt = 0; nt < 8; nt++)
        #pragma unroll
        for (int i = 0; i < 4; i++) c[nt][i] = 0.f;

    #pragma unroll
    for (int kt = 0; kt < 16; kt++) {
        int s  = kt >> 2;
        const __half* A = (s == 0) ? g_xh : (g_aggh + (s-1)*(ROWS*Hh));
        int kk = (kt & 3)*16 + qc*2;
        uint32_t a0 = *(const uint32_t*)(A + rowA*64 + kk);
        uint32_t a1 = *(const uint32_t*)(A + (rowA+8)*64 + kk);
        uint32_t a2 = *(const uint32_t*)(A + rowA*64 + kk + 8);
        uint32_t a3 = *(const uint32_t*)(A + (rowA+8)*64 + kk + 8);
        #pragma unroll
        for (int nt = 0; nt < 8; nt++) {
            uint2 b = sB[(kt*8 + nt)*32 + lane];
            asm volatile(
                "mma.sync.aligned.m16n8k16.row.col.f32.f16.f16.f32 "
                "{%0,%1,%2,%3}, {%4,%5,%6,%7}, {%8,%9}, {%0,%1,%2,%3};"
                : "+f"(c[nt][0]), "+f"(c[nt][1]), "+f"(c[nt][2]), "+f"(c[nt][3])
                : "r"(a0), "r"(a1), "r"(a2), "r"(a3), "r"(b.x), "r"(b.y));
        }
    }

    #pragma unroll
    for (int h = 0; h < 2; h++) {
        int row = rowA + h*8;
        float sum = 0.f, sq = 0.f;
        #pragma unroll
        for (int nt = 0; nt < 8; nt++) {
            float v0 = c[nt][2*h], v1 = c[nt][2*h + 1];
            sum += v0 + v1;
            sq   = fmaf(v0, v0, fmaf(v1, v1, sq));
        }
        sum += __shfl_xor_sync(0xffffffffu, sum, 1);
        sq  += __shfl_xor_sync(0xffffffffu, sq, 1);
        sum += __shfl_xor_sync(0xffffffffu, sum, 2);
        sq  += __shfl_xor_sync(0xffffffffu, sq, 2);
        float mu  = sum * (1.f/64.f);
        float var = sq  * (1.f/64.f) - mu*mu;
        float inv = rsqrtf(var + LN_EPS);
        if (!final_layer) {
            #pragma unroll
            for (int nt = 0; nt < 8; nt++) {
                int col = nt*8 + qc*2;
                float o0 = fmaxf(fmaf((c[nt][2*h]  -mu)*inv, sLN[col],   sLN[64+col]),   0.f);
                float o1 = fmaxf(fmaf((c[nt][2*h+1]-mu)*inv, sLN[col+1], sLN[64+col+1]), 0.f);
                __half2 hv = __floats2half2_rn(o0, o1);
                *(unsigned*)(g_xh + row*64 + col) = *(unsigned*)&hv;
            }
        } else {
            float dot = 0.f;
            #pragma unroll
            for (int nt = 0; nt < 8; nt++) {
                int col = nt*8 + qc*2;
                float o0 = fmaxf(fmaf((c[nt][2*h]  -mu)*inv, sLN[col],   sLN[64+col]),   0.f);
                float o1 = fmaxf(fmaf((c[nt][2*h+1]-mu)*inv, sLN[col+1], sLN[64+col+1]), 0.f);
                dot = fmaf(o0, sLN[128+col], fmaf(o1, sLN[128+col+1], dot));
            }
            dot += __shfl_xor_sync(0xffffffffu, dot, 1);
            dot += __shfl_xor_sync(0xffffffffu, dot, 2);
            if (qc == 0) {
                int b = row & 7, n = row >> 3;
                out[b*Nn + n] = dot + sLN[192];
            }
        }
    }
}

// ---------------- launch ----------------
extern "C" void kernel_launch(void* const* d_in, const int* in_sizes, int n_in,
                              void* d_out, int out_size)
{
    const float* ctl      = (const float*)d_in[0];
    const float* drug     = (const float*)d_in[1];
    const float* fp       = (const float*)d_in[2];
    const float* ew       = (const float*)d_in[3];
    const int*   cell_idx = (const int*)  d_in[4];
    const int*   ei       = (const int*)  d_in[5];
    const float* W_se     = (const float*)d_in[6];
    const float* b_se     = (const float*)d_in[7];
    const float* cell_emb = (const float*)d_in[8];
    const float* W_f1     = (const float*)d_in[9];
    const float* b_f1     = (const float*)d_in[10];
    const float* W_f2     = (const float*)d_in[11];
    const float* b_f2     = (const float*)d_in[12];
    const float* Wself    = (const float*)d_in[13];
    const float* Wrel     = (const float*)d_in[14];
    const float* ln_g     = (const float*)d_in[15];
    const float* ln_b     = (const float*)d_in[16];
    const float* W_out    = (const float*)d_in[17];
    const float* b_out    = (const float*)d_in[18];
    float* out = (float*)d_out;

    int npre = Rr*ESEG + Bn + (Ll*16*8*32 + 1023)/1024;   // 24 + 8 + 16 = 48
    pre_kernel<<<npre, 1024>>>(ei, fp, W_f1, b_f1, W_f2, b_f2, Wself, Wrel); // 1
    scan_kernel<<<Rr, 1024>>>();                                             // 2
    init_x_kernel<<<(ROWS*Hh + 255)/256, 256>>>(ctl, drug, W_se, b_se,
                                                cell_emb, cell_idx);         // 3
    fill_kernel<<<Rr*ESEG, 1024>>>(ei, ew);                                  // 4 <- profiled

    for (int l = 0; l < Ll; l++) {
        gather_kernel<<<dim3(Nn, Rr), 64>>>();
        gemm_mma_kernel<<<ROWS/128, 256>>>(ln_g, ln_b, W_out, b_out, out,
                                           l, (l == Ll-1) ? 1 : 0);
    }
}

// round 10
// speedup vs baseline: 3.3395x; 1.1571x over previous
#include <cuda_runtime.h>
#include <cuda_fp16.h>
#include <math.h>
#include <stdint.h>

#define Bn 8
#define Nn 10000
#define Hh 64
#define Ll 4
#define Rr 3
#define Ee 200000
#define FPn 2048
#define ROWS (Nn*Bn)            /* 80000 rows; row m = node*8 + b */
#define LN_EPS 1e-3f
#define ESEG 8                  /* hist blocks per relation */
#define ECHUNK (Ee/ESEG)        /* 25000 */
#define FSEG 64                 /* fill blocks per relation */
#define FCHUNK (Ee/FSEG)        /* 3125 */

// ---------------- device scratch ----------------
__device__ __half g_xh[ROWS*Hh];            // x (fp16) — single state buffer
__device__ __half g_aggh[Rr*ROWS*Hh];       // per-relation aggregation (fp16)
__device__ uint2  g_bfrag[Ll*16*8*32];      // B in exact mma-fragment order
__device__ float  g_film[Bn*2*Hh];
__device__ int    g_hist[Rr*Nn];            // degree hist (re-zeroed by scan)
__device__ int    g_rowptr[Rr*(Nn+1)];
__device__ int    g_cnt[Rr*Nn];             // atomic fill cursors
__device__ int4   g_epk[Rr*Ee];             // CSR packed (src, 0, wbits, wbits)

// ---------------- packed f32x2 fma ----------------
__device__ __forceinline__ unsigned long long ffma2u(unsigned long long a,
                                                     unsigned long long b,
                                                     unsigned long long c)
{
    unsigned long long d;
    asm("fma.rn.f32x2 %0, %1, %2, %3;" : "=l"(d) : "l"(a), "l"(b), "l"(c));
    return d;
}
__device__ __forceinline__ unsigned long long pack64(float lo, float hi)
{
    unsigned long long u;
    asm("mov.b64 %0, {%1, %2};" : "=l"(u) : "f"(lo), "f"(hi));
    return u;
}

// ---------------- pre-kernel: hist(24) + film(8) + prep_b(16) ---------------
__global__ __launch_bounds__(1024)
void pre_kernel(const int* __restrict__ ei,
                const float* __restrict__ fp,
                const float* __restrict__ W1, const float* __restrict__ b1,
                const float* __restrict__ W2, const float* __restrict__ b2,
                const float* __restrict__ Wself, const float* __restrict__ Wrel)
{
    __shared__ int   sh[Nn];
    __shared__ float part[1024];
    __shared__ float hid[64];
    int bk = blockIdx.x, t = threadIdx.x;

    if (bk < Rr*ESEG) {
        int r = bk / ESEG, seg = bk % ESEG;
        for (int i = t; i < Nn; i += 1024) sh[i] = 0;
        __syncthreads();
        const int* dstp = ei + (r*2 + 1)*Ee + seg*ECHUNK;
        for (int e = t; e < ECHUNK; e += 1024) atomicAdd(&sh[dstp[e]], 1);
        __syncthreads();
        for (int i = t; i < Nn; i += 1024) {
            int v = sh[i];
            if (v) atomicAdd(&g_hist[r*Nn + i], v);
        }
    } else if (bk < Rr*ESEG + Bn) {
        int b = bk - Rr*ESEG;
        int h = t >> 4, kc = t & 15;
        const float* fpb = fp + b*FPn;
        float a0 = 0.f, a1 = 0.f;
        int k0 = kc*128;
        for (int k = k0; k < k0 + 128; k += 2) {
            a0 = fmaf(fpb[k],   W1[k*Hh + h],     a0);
            a1 = fmaf(fpb[k+1], W1[(k+1)*Hh + h], a1);
        }
        part[t] = a0 + a1;
        __syncthreads();
        if (t < 64) {
            float a = b1[t];
            #pragma unroll
            for (int i = 0; i < 16; i++) a += part[t*16 + i];
            hid[t] = fmaxf(a, 0.f);
        }
        __syncthreads();
        if (t < 128) {
            int j = t;
            float a = b2[j];
            #pragma unroll
            for (int k = 0; k < Hh; k++) a += hid[k] * W2[k*128 + j];
            if (j < 64) g_film[b*128 + j] = 1.f + tanhf(a);
            else        g_film[b*128 + j] = a;
        }
    } else {
        int idx = (bk - Rr*ESEG - Bn)*1024 + t;
        if (idx < Ll*16*8*32) {
            int l    = idx >> 12;
            int kt   = (idx >> 8) & 15;
            int nt   = (idx >> 5) & 7;
            int lane = idx & 31;
            int s  = kt >> 2;
            int kb = (kt & 3)*16 + (lane & 3)*2;
            int n  = nt*8 + (lane >> 2);
            const float* W = (s == 0) ? (Wself + l*4096) : (Wrel + (l*Rr + s-1)*4096);
            __half2 lo = __floats2half2_rn(W[kb*64 + n],     W[(kb+1)*64 + n]);
            __half2 hi = __floats2half2_rn(W[(kb+8)*64 + n], W[(kb+9)*64 + n]);
            uint2 u;
            u.x = *(unsigned*)&lo;
            u.y = *(unsigned*)&hi;
            g_bfrag[idx] = u;
        }
    }
}

// ---------------- scan: rowptr + cursors; re-zeros g_hist -------------------
__global__ __launch_bounds__(1024)
void scan_kernel()   // grid = Rr x 1024
{
    __shared__ int wsum[32];
    int r = blockIdx.x, t = threadIdx.x;
    int lane = t & 31, warp = t >> 5;
    int carry = 0;
    if (t == 0) g_rowptr[r*(Nn+1)] = 0;
    for (int base = 0; base < Nn; base += 1024) {
        int idx = base + t;
        int v = (idx < Nn) ? g_hist[r*Nn + idx] : 0;
        int s = v;
        #pragma unroll
        for (int off = 1; off < 32; off <<= 1) {
            int nbr = __shfl_up_sync(0xffffffffu, s, off);
            if (lane >= off) s += nbr;
        }
        if (lane == 31) wsum[warp] = s;
        __syncthreads();
        if (warp == 0) {
            int w = wsum[lane];
            #pragma unroll
            for (int off = 1; off < 32; off <<= 1) {
                int nbr = __shfl_up_sync(0xffffffffu, w, off);
                if (lane >= off) w += nbr;
            }
            wsum[lane] = w;
        }
        __syncthreads();
        int tot = carry + (warp ? wsum[warp-1] : 0) + s;
        if (idx < Nn) {
            g_rowptr[r*(Nn+1) + idx + 1] = tot;
            g_cnt[r*Nn + idx]  = tot - v;
            g_hist[r*Nn + idx] = 0;
        }
        carry += wsum[31];
        __syncthreads();
    }
}

// ---------------- fill: 192 blocks x 256, global atomic cursors -------------
__global__ __launch_bounds__(256)
void fill_kernel(const int* __restrict__ ei, const float* __restrict__ ew)
{
    int bk = blockIdx.x, t = threadIdx.x;
    int r = bk / FSEG, seg = bk % FSEG;
    const int* dstp = ei + (r*2 + 1)*Ee + seg*FCHUNK;
    const int* srcp = ei + (r*2 + 0)*Ee + seg*FCHUNK;
    const float* wp = ew + r*Ee + seg*FCHUNK;
    for (int e = t; e < FCHUNK; e += 256) {
        int dst = dstp[e];
        int pos = atomicAdd(&g_cnt[r*Nn + dst], 1);
        int wb  = __float_as_int(wp[e]);
        g_epk[r*Ee + pos] = make_int4(srcp[e], 0, wb, wb);
    }
}

// ---------------- initial node features (uint4 stores) ----------------------
__global__ void init_x_kernel(const float* __restrict__ ctl, const float* __restrict__ drug,
                              const float* __restrict__ W_se, const float* __restrict__ b_se,
                              const float* __restrict__ cell_emb, const int* __restrict__ cell_idx)
{
    int i = blockIdx.x*blockDim.x + threadIdx.x;   // (m, q): 8 halfs each
    if (i >= ROWS*8) return;
    int q = i & 7;
    int m = i >> 3;
    int b = m & 7;
    int n = m >> 3;
    float v1 = ctl[b*Nn + n], v2 = drug[b*Nn + n];
    const float* ce = cell_emb + cell_idx[b]*Hh + q*8;
    const float* ws = W_se + q*8;
    const float* bs = b_se + q*8;
    const float* fg = g_film + b*128 + q*8;
    uint4 outv;
    unsigned* op = (unsigned*)&outv;
    #pragma unroll
    for (int p = 0; p < 4; p++) {
        float o[2];
        #pragma unroll
        for (int e = 0; e < 2; e++) {
            int h = p*2 + e;
            float w = ws[h], bb = bs[h];
            float xv = fmaxf(fmaf(v1, w, bb), 0.f) + fmaxf(fmaf(v2, w, bb), 0.f);
            xv += ce[h];
            o[e] = fmaf(xv, fg[h], fg[64 + h]);
        }
        __half2 hv = __floats2half2_rn(o[0], o[1]);
        op[p] = *(unsigned*)&hv;
    }
    ((uint4*)g_xh)[i] = outv;
}

// ---------------- gather: 64 thr x uint4, FFMA2, smem meta ------------------
#define GCH 128
__device__ __forceinline__ void macc8(unsigned long long* acc, uint4 v,
                                      unsigned long long w2)
{
    float2 f0 = __half22float2(*(__half2*)&v.x);
    float2 f1 = __half22float2(*(__half2*)&v.y);
    float2 f2 = __half22float2(*(__half2*)&v.z);
    float2 f3 = __half22float2(*(__half2*)&v.w);
    acc[0] = ffma2u(pack64(f0.x, f0.y), w2, acc[0]);
    acc[1] = ffma2u(pack64(f1.x, f1.y), w2, acc[1]);
    acc[2] = ffma2u(pack64(f2.x, f2.y), w2, acc[2]);
    acc[3] = ffma2u(pack64(f3.x, f3.y), w2, acc[3]);
}

__global__ __launch_bounds__(64)
void gather_kernel()  // grid (Nn, Rr) x 64
{
    __shared__ int4 sM[GCH];
    int dst = blockIdx.x, r = blockIdx.y;
    int t = threadIdx.x;
    int start = g_rowptr[r*(Nn+1) + dst];
    int end   = g_rowptr[r*(Nn+1) + dst + 1];
    const uint4* __restrict__ xq = (const uint4*)g_xh;
    const int4*  __restrict__ ep = g_epk + r*Ee;
    unsigned long long acc[4] = {0ull, 0ull, 0ull, 0ull};

    for (int base = start; base < end; base += GCH) {
        int n = min(GCH, end - base);
        if (t < n)       sM[t]      = ep[base + t];
        if (t + 64 < n)  sM[t + 64] = ep[base + t + 64];
        __syncthreads();
        int j = 0;
        for (; j + 4 <= n; j += 4) {
            int4 m0 = sM[j], m1 = sM[j+1], m2 = sM[j+2], m3 = sM[j+3];
            uint4 v0 = xq[m0.x*64 + t];
            uint4 v1 = xq[m1.x*64 + t];
            uint4 v2 = xq[m2.x*64 + t];
            uint4 v3 = xq[m3.x*64 + t];
            macc8(acc, v0, *(unsigned long long*)&m0.z);
            macc8(acc, v1, *(unsigned long long*)&m1.z);
            macc8(acc, v2, *(unsigned long long*)&m2.z);
            macc8(acc, v3, *(unsigned long long*)&m3.z);
        }
        for (; j < n; j++) {
            int4 m0 = sM[j];
            uint4 v0 = xq[m0.x*64 + t];
            macc8(acc, v0, *(unsigned long long*)&m0.z);
        }
        __syncthreads();
    }

    uint4 hw;
    unsigned* hp = (unsigned*)&hw;
    #pragma unroll
    for (int q = 0; q < 4; q++) {
        float2 f = *(float2*)&acc[q];
        __half2 h = __floats2half2_rn(f.x, f.y);
        hp[q] = *(unsigned*)&h;
    }
    ((uint4*)(g_aggh + r*(ROWS*Hh) + dst*512))[t] = hw;
}

// ---------------- HMMA GEMM (smem-staged A) + LN + ReLU (+ fused out) -------
__global__ __launch_bounds__(256)
void gemm_mma_kernel(const float* __restrict__ ln_g, const float* __restrict__ ln_b,
                     const float* __restrict__ W_out, const float* __restrict__ b_out,
                     float* __restrict__ out, int layer, int final_layer)
{
    __shared__ __half sA[128][72];    // padded: row stride 36 words -> conflict-free frags
    __shared__ uint2  sBs[4*8*32];    // B frags for current stream (8KB)
    __shared__ float  sLN[194];       // gamma | beta | W_out | b_out

    int tid = threadIdx.x;
    int wid = tid >> 5, lane = tid & 31;
    int qr = lane >> 2, qc = lane & 3;

    if (tid < 64)        sLN[tid] = ln_g[layer*64 + tid];
    else if (tid < 128)  sLN[tid] = ln_b[layer*64 + tid - 64];
    else if (tid < 192)  sLN[tid] = W_out[tid - 128];
    else if (tid == 192) sLN[192] = b_out[0];

    int m0 = blockIdx.x*128;
    int rl = wid*16 + qr;             // local row in tile

    float c[8][4];
    #pragma unroll
    for (int nt = 0; nt < 8; nt++)
        #pragma unroll
        for (int i = 0; i < 4; i++) c[nt][i] = 0.f;

    for (int s = 0; s < 4; s++) {
        const uint4* Asrc = (const uint4*)(((s == 0) ? g_xh
                                : (g_aggh + (s-1)*(ROWS*Hh))) + m0*64);
        #pragma unroll
        for (int i = tid; i < 1024; i += 256) {
            int row = i >> 3, cq = i & 7;
            *(uint4*)&sA[row][cq*8] = Asrc[i];
        }
        const uint4* bsrc = (const uint4*)(g_bfrag + layer*4096 + s*1024);
        #pragma unroll
        for (int i = tid; i < 512; i += 256) ((uint4*)sBs)[i] = bsrc[i];
        __syncthreads();

        #pragma unroll
        for (int kti = 0; kti < 4; kti++) {
            int kh = kti*16 + qc*2;
            uint32_t a0 = *(const uint32_t*)&sA[rl][kh];
            uint32_t a1 = *(const uint32_t*)&sA[rl + 8][kh];
            uint32_t a2 = *(const uint32_t*)&sA[rl][kh + 8];
            uint32_t a3 = *(const uint32_t*)&sA[rl + 8][kh + 8];
            #pragma unroll
            for (int nt = 0; nt < 8; nt++) {
                uint2 b = sBs[(kti*8 + nt)*32 + lane];
                asm volatile(
                    "mma.sync.aligned.m16n8k16.row.col.f32.f16.f16.f32 "
                    "{%0,%1,%2,%3}, {%4,%5,%6,%7}, {%8,%9}, {%0,%1,%2,%3};"
                    : "+f"(c[nt][0]), "+f"(c[nt][1]), "+f"(c[nt][2]), "+f"(c[nt][3])
                    : "r"(a0), "r"(a1), "r"(a2), "r"(a3), "r"(b.x), "r"(b.y));
            }
        }
        __syncthreads();
    }

    #pragma unroll
    for (int h = 0; h < 2; h++) {
        int row = m0 + rl + h*8;
        float sum = 0.f, sq = 0.f;
        #pragma unroll
        for (int nt = 0; nt < 8; nt++) {
            float v0 = c[nt][2*h], v1 = c[nt][2*h + 1];
            sum += v0 + v1;
            sq   = fmaf(v0, v0, fmaf(v1, v1, sq));
        }
        sum += __shfl_xor_sync(0xffffffffu, sum, 1);
        sq  += __shfl_xor_sync(0xffffffffu, sq, 1);
        sum += __shfl_xor_sync(0xffffffffu, sum, 2);
        sq  += __shfl_xor_sync(0xffffffffu, sq, 2);
        float mu  = sum * (1.f/64.f);
        float var = sq  * (1.f/64.f) - mu*mu;
        float inv = rsqrtf(var + LN_EPS);
        if (!final_layer) {
            #pragma unroll
            for (int nt = 0; nt < 8; nt++) {
                int col = nt*8 + qc*2;
                float o0 = fmaxf(fmaf((c[nt][2*h]  -mu)*inv, sLN[col],   sLN[64+col]),   0.f);
                float o1 = fmaxf(fmaf((c[nt][2*h+1]-mu)*inv, sLN[col+1], sLN[64+col+1]), 0.f);
                __half2 hv = __floats2half2_rn(o0, o1);
                *(unsigned*)(g_xh + row*64 + col) = *(unsigned*)&hv;
            }
        } else {
            float dot = 0.f;
            #pragma unroll
            for (int nt = 0; nt < 8; nt++) {
                int col = nt*8 + qc*2;
                float o0 = fmaxf(fmaf((c[nt][2*h]  -mu)*inv, sLN[col],   sLN[64+col]),   0.f);
                float o1 = fmaxf(fmaf((c[nt][2*h+1]-mu)*inv, sLN[col+1], sLN[64+col+1]), 0.f);
                dot = fmaf(o0, sLN[128+col], fmaf(o1, sLN[128+col+1], dot));
            }
            dot += __shfl_xor_sync(0xffffffffu, dot, 1);
            dot += __shfl_xor_sync(0xffffffffu, dot, 2);
            if (qc == 0) {
                int b = row & 7, n = row >> 3;
                out[b*Nn + n] = dot + sLN[192];
            }
        }
    }
}

// ---------------- launch ----------------
extern "C" void kernel_launch(void* const* d_in, const int* in_sizes, int n_in,
                              void* d_out, int out_size)
{
    const float* ctl      = (const float*)d_in[0];
    const float* drug     = (const float*)d_in[1];
    const float* fp       = (const float*)d_in[2];
    const float* ew       = (const float*)d_in[3];
    const int*   cell_idx = (const int*)  d_in[4];
    const int*   ei       = (const int*)  d_in[5];
    const float* W_se     = (const float*)d_in[6];
    const float* b_se     = (const float*)d_in[7];
    const float* cell_emb = (const float*)d_in[8];
    const float* W_f1     = (const float*)d_in[9];
    const float* b_f1     = (const float*)d_in[10];
    const float* W_f2     = (const float*)d_in[11];
    const float* b_f2     = (const float*)d_in[12];
    const float* Wself    = (const float*)d_in[13];
    const float* Wrel     = (const float*)d_in[14];
    const float* ln_g     = (const float*)d_in[15];
    const float* ln_b     = (const float*)d_in[16];
    const float* W_out    = (const float*)d_in[17];
    const float* b_out    = (const float*)d_in[18];
    float* out = (float*)d_out;

    int npre = Rr*ESEG + Bn + (Ll*16*8*32 + 1023)/1024;   // 24 + 8 + 16 = 48
    pre_kernel<<<npre, 1024>>>(ei, fp, W_f1, b_f1, W_f2, b_f2, Wself, Wrel); // 1
    scan_kernel<<<Rr, 1024>>>();                                             // 2
    fill_kernel<<<Rr*FSEG, 256>>>(ei, ew);                                   // 3
    init_x_kernel<<<(ROWS*8 + 255)/256, 256>>>(ctl, drug, W_se, b_se,
                                               cell_emb, cell_idx);          // 4

    for (int l = 0; l < Ll; l++) {
        gather_kernel<<<dim3(Nn, Rr), 64>>>();
        gemm_mma_kernel<<<ROWS/128, 256>>>(ln_g, ln_b, W_out, b_out, out,
                                           l, (l == Ll-1) ? 1 : 0);
    }
}

// round 11
// speedup vs baseline: 3.4018x; 1.0186x over previous
#include <cuda_runtime.h>
#include <cuda_fp16.h>
#include <math.h>
#include <stdint.h>

#define Bn 8
#define Nn 10000
#define Hh 64
#define Ll 4
#define Rr 3
#define Ee 200000
#define FPn 2048
#define ROWS (Nn*Bn)            /* 80000 rows; row m = node*8 + b */
#define LN_EPS 1e-3f
#define ESEG 8                  /* hist blocks per relation */
#define ECHUNK (Ee/ESEG)        /* 25000 */
#define FSEG 64                 /* fill blocks per relation */
#define FCHUNK (Ee/FSEG)        /* 3125 */
#define FILLB (Rr*FSEG)         /* 192 fill blocks */

// ---------------- device scratch ----------------
__device__ __half g_xh[ROWS*Hh];            // x (fp16) — single state buffer
__device__ __half g_aggh[Rr*ROWS*Hh];       // per-relation aggregation (fp16)
__device__ uint2  g_bfrag[Ll*16*8*32];      // B in exact mma-fragment order
__device__ float  g_film[Bn*2*Hh];
__device__ int    g_hist[Rr*Nn];            // degree hist (re-zeroed by scan)
__device__ int    g_rowptr[Rr*(Nn+1)];
__device__ int    g_cnt[Rr*Nn];             // atomic fill cursors
__device__ int4   g_epk[Rr*Ee];             // CSR packed (src, 0, wbits, wbits)

// ---------------- packed f32x2 fma ----------------
__device__ __forceinline__ unsigned long long ffma2u(unsigned long long a,
                                                     unsigned long long b,
                                                     unsigned long long c)
{
    unsigned long long d;
    asm("fma.rn.f32x2 %0, %1, %2, %3;" : "=l"(d) : "l"(a), "l"(b), "l"(c));
    return d;
}
__device__ __forceinline__ unsigned long long pack64(float lo, float hi)
{
    unsigned long long u;
    asm("mov.b64 %0, {%1, %2};" : "=l"(u) : "f"(lo), "f"(hi));
    return u;
}

// ---------------- pre-kernel: hist(24) + film(8) + prep_b(16) ---------------
__global__ __launch_bounds__(1024)
void pre_kernel(const int* __restrict__ ei,
                const float* __restrict__ fp,
                const float* __restrict__ W1, const float* __restrict__ b1,
                const float* __restrict__ W2, const float* __restrict__ b2,
                const float* __restrict__ Wself, const float* __restrict__ Wrel)
{
    __shared__ int   sh[Nn];
    __shared__ float part[1024];
    __shared__ float hid[64];
    int bk = blockIdx.x, t = threadIdx.x;

    if (bk < Rr*ESEG) {
        int r = bk / ESEG, seg = bk % ESEG;
        for (int i = t; i < Nn; i += 1024) sh[i] = 0;
        __syncthreads();
        const int* dstp = ei + (r*2 + 1)*Ee + seg*ECHUNK;
        for (int e = t; e < ECHUNK; e += 1024) atomicAdd(&sh[dstp[e]], 1);
        __syncthreads();
        for (int i = t; i < Nn; i += 1024) {
            int v = sh[i];
            if (v) atomicAdd(&g_hist[r*Nn + i], v);
        }
    } else if (bk < Rr*ESEG + Bn) {
        int b = bk - Rr*ESEG;
        int h = t >> 4, kc = t & 15;
        const float* fpb = fp + b*FPn;
        float a0 = 0.f, a1 = 0.f;
        int k0 = kc*128;
        for (int k = k0; k < k0 + 128; k += 2) {
            a0 = fmaf(fpb[k],   W1[k*Hh + h],     a0);
            a1 = fmaf(fpb[k+1], W1[(k+1)*Hh + h], a1);
        }
        part[t] = a0 + a1;
        __syncthreads();
        if (t < 64) {
            float a = b1[t];
            #pragma unroll
            for (int i = 0; i < 16; i++) a += part[t*16 + i];
            hid[t] = fmaxf(a, 0.f);
        }
        __syncthreads();
        if (t < 128) {
            int j = t;
            float a = b2[j];
            #pragma unroll
            for (int k = 0; k < Hh; k++) a += hid[k] * W2[k*128 + j];
            if (j < 64) g_film[b*128 + j] = 1.f + tanhf(a);
            else        g_film[b*128 + j] = a;
        }
    } else {
        int idx = (bk - Rr*ESEG - Bn)*1024 + t;
        if (idx < Ll*16*8*32) {
            int l    = idx >> 12;
            int kt   = (idx >> 8) & 15;
            int nt   = (idx >> 5) & 7;
            int lane = idx & 31;
            int s  = kt >> 2;
            int kb = (kt & 3)*16 + (lane & 3)*2;
            int n  = nt*8 + (lane >> 2);
            const float* W = (s == 0) ? (Wself + l*4096) : (Wrel + (l*Rr + s-1)*4096);
            __half2 lo = __floats2half2_rn(W[kb*64 + n],     W[(kb+1)*64 + n]);
            __half2 hi = __floats2half2_rn(W[(kb+8)*64 + n], W[(kb+9)*64 + n]);
            uint2 u;
            u.x = *(unsigned*)&lo;
            u.y = *(unsigned*)&hi;
            g_bfrag[idx] = u;
        }
    }
}

// ---------------- scan: rowptr + cursors; re-zeros g_hist -------------------
__global__ __launch_bounds__(1024)
void scan_kernel()   // grid = Rr x 1024
{
    __shared__ int wsum[32];
    int r = blockIdx.x, t = threadIdx.x;
    int lane = t & 31, warp = t >> 5;
    int carry = 0;
    if (t == 0) g_rowptr[r*(Nn+1)] = 0;
    for (int base = 0; base < Nn; base += 1024) {
        int idx = base + t;
        int v = (idx < Nn) ? g_hist[r*Nn + idx] : 0;
        int s = v;
        #pragma unroll
        for (int off = 1; off < 32; off <<= 1) {
            int nbr = __shfl_up_sync(0xffffffffu, s, off);
            if (lane >= off) s += nbr;
        }
        if (lane == 31) wsum[warp] = s;
        __syncthreads();
        if (warp == 0) {
            int w = wsum[lane];
            #pragma unroll
            for (int off = 1; off < 32; off <<= 1) {
                int nbr = __shfl_up_sync(0xffffffffu, w, off);
                if (lane >= off) w += nbr;
            }
            wsum[lane] = w;
        }
        __syncthreads();
        int tot = carry + (warp ? wsum[warp-1] : 0) + s;
        if (idx < Nn) {
            g_rowptr[r*(Nn+1) + idx + 1] = tot;
            g_cnt[r*Nn + idx]  = tot - v;
            g_hist[r*Nn + idx] = 0;
        }
        carry += wsum[31];
        __syncthreads();
    }
}

// ---------------- fused fill(192) + init(2500) ------------------------------
__global__ __launch_bounds__(256)
void fillinit_kernel(const int* __restrict__ ei, const float* __restrict__ ew,
                     const float* __restrict__ ctl, const float* __restrict__ drug,
                     const float* __restrict__ W_se, const float* __restrict__ b_se,
                     const float* __restrict__ cell_emb, const int* __restrict__ cell_idx)
{
    int bk = blockIdx.x, t = threadIdx.x;
    if (bk < FILLB) {
        // ---- CSR fill with global atomic cursors ----
        int r = bk / FSEG, seg = bk % FSEG;
        const int* dstp = ei + (r*2 + 1)*Ee + seg*FCHUNK;
        const int* srcp = ei + (r*2 + 0)*Ee + seg*FCHUNK;
        const float* wp = ew + r*Ee + seg*FCHUNK;
        for (int e = t; e < FCHUNK; e += 256) {
            int dst = dstp[e];
            int pos = atomicAdd(&g_cnt[r*Nn + dst], 1);
            int wb  = __float_as_int(wp[e]);
            g_epk[r*Ee + pos] = make_int4(srcp[e], 0, wb, wb);
        }
        return;
    }
    // ---- init x: params staged in smem ----
    // layout: sW[64] | sBb[64] | sCE[8*64] | sG[8*64] | sBeta[8*64]  (1664 f)
    __shared__ float sp[1664];
    for (int i = t; i < 1664; i += 256) {
        float v;
        if (i < 64)        v = W_se[i];
        else if (i < 128)  v = b_se[i - 64];
        else if (i < 640) {
            int j = i - 128, b = j >> 6, h = j & 63;
            v = cell_emb[cell_idx[b]*Hh + h];
        } else if (i < 1152) {
            int j = i - 640, b = j >> 6, h = j & 63;
            v = g_film[b*128 + h];            // gamma' = 1+tanh
        } else {
            int j = i - 1152, b = j >> 6, h = j & 63;
            v = g_film[b*128 + 64 + h];       // beta
        }
        sp[i] = v;
    }
    __syncthreads();

    int i = (bk - FILLB)*256 + t;              // (m, q): 8 halfs each
    if (i >= ROWS*8) return;
    int q = i & 7;
    int m = i >> 3;
    int b = m & 7;
    int n = m >> 3;
    float v1 = ctl[b*Nn + n], v2 = drug[b*Nn + n];
    const float4* w4  = (const float4*)&sp[q*8];
    const float4* bb4 = (const float4*)&sp[64 + q*8];
    const float4* ce4 = (const float4*)&sp[128 + b*64 + q*8];
    const float4* g4  = (const float4*)&sp[640 + b*64 + q*8];
    const float4* be4 = (const float4*)&sp[1152 + b*64 + q*8];
    uint4 outv;
    unsigned* op = (unsigned*)&outv;
    #pragma unroll
    for (int p = 0; p < 2; p++) {
        float4 w = w4[p], bb = bb4[p], ce = ce4[p], gg = g4[p], be = be4[p];
        float o[4];
        o[0] = fmaf(fmaxf(fmaf(v1, w.x, bb.x), 0.f) + fmaxf(fmaf(v2, w.x, bb.x), 0.f) + ce.x, gg.x, be.x);
        o[1] = fmaf(fmaxf(fmaf(v1, w.y, bb.y), 0.f) + fmaxf(fmaf(v2, w.y, bb.y), 0.f) + ce.y, gg.y, be.y);
        o[2] = fmaf(fmaxf(fmaf(v1, w.z, bb.z), 0.f) + fmaxf(fmaf(v2, w.z, bb.z), 0.f) + ce.z, gg.z, be.z);
        o[3] = fmaf(fmaxf(fmaf(v1, w.w, bb.w), 0.f) + fmaxf(fmaf(v2, w.w, bb.w), 0.f) + ce.w, gg.w, be.w);
        __half2 h0 = __floats2half2_rn(o[0], o[1]);
        __half2 h1 = __floats2half2_rn(o[2], o[3]);
        op[p*2]   = *(unsigned*)&h0;
        op[p*2+1] = *(unsigned*)&h1;
    }
    ((uint4*)g_xh)[i] = outv;
}

// ---------------- gather: 64 thr x uint4, FFMA2, 8-deep MLP -----------------
#define GCH 128
__device__ __forceinline__ void macc8(unsigned long long* acc, uint4 v,
                                      unsigned long long w2)
{
    float2 f0 = __half22float2(*(__half2*)&v.x);
    float2 f1 = __half22float2(*(__half2*)&v.y);
    float2 f2 = __half22float2(*(__half2*)&v.z);
    float2 f3 = __half22float2(*(__half2*)&v.w);
    acc[0] = ffma2u(pack64(f0.x, f0.y), w2, acc[0]);
    acc[1] = ffma2u(pack64(f1.x, f1.y), w2, acc[1]);
    acc[2] = ffma2u(pack64(f2.x, f2.y), w2, acc[2]);
    acc[3] = ffma2u(pack64(f3.x, f3.y), w2, acc[3]);
}

__global__ __launch_bounds__(64)
void gather_kernel()  // grid (Nn, Rr) x 64
{
    __shared__ int4 sM[GCH];
    int dst = blockIdx.x, r = blockIdx.y;
    int t = threadIdx.x;
    int start = g_rowptr[r*(Nn+1) + dst];
    int end   = g_rowptr[r*(Nn+1) + dst + 1];
    const uint4* __restrict__ xq = (const uint4*)g_xh;
    const int4*  __restrict__ ep = g_epk + r*Ee;
    unsigned long long acc[4] = {0ull, 0ull, 0ull, 0ull};

    for (int base = start; base < end; base += GCH) {
        int n = min(GCH, end - base);
        if (t < n)       sM[t]      = ep[base + t];
        if (t + 64 < n)  sM[t + 64] = ep[base + t + 64];
        __syncthreads();
        int j = 0;
        for (; j + 8 <= n; j += 8) {
            int4 m0 = sM[j],   m1 = sM[j+1], m2 = sM[j+2], m3 = sM[j+3];
            int4 m4 = sM[j+4], m5 = sM[j+5], m6 = sM[j+6], m7 = sM[j+7];
            uint4 v0 = xq[m0.x*64 + t];
            uint4 v1 = xq[m1.x*64 + t];
            uint4 v2 = xq[m2.x*64 + t];
            uint4 v3 = xq[m3.x*64 + t];
            uint4 v4 = xq[m4.x*64 + t];
            uint4 v5 = xq[m5.x*64 + t];
            uint4 v6 = xq[m6.x*64 + t];
            uint4 v7 = xq[m7.x*64 + t];
            macc8(acc, v0, *(unsigned long long*)&m0.z);
            macc8(acc, v1, *(unsigned long long*)&m1.z);
            macc8(acc, v2, *(unsigned long long*)&m2.z);
            macc8(acc, v3, *(unsigned long long*)&m3.z);
            macc8(acc, v4, *(unsigned long long*)&m4.z);
            macc8(acc, v5, *(unsigned long long*)&m5.z);
            macc8(acc, v6, *(unsigned long long*)&m6.z);
            macc8(acc, v7, *(unsigned long long*)&m7.z);
        }
        for (; j + 4 <= n; j += 4) {
            int4 m0 = sM[j], m1 = sM[j+1], m2 = sM[j+2], m3 = sM[j+3];
            uint4 v0 = xq[m0.x*64 + t];
            uint4 v1 = xq[m1.x*64 + t];
            uint4 v2 = xq[m2.x*64 + t];
            uint4 v3 = xq[m3.x*64 + t];
            macc8(acc, v0, *(unsigned long long*)&m0.z);
            macc8(acc, v1, *(unsigned long long*)&m1.z);
            macc8(acc, v2, *(unsigned long long*)&m2.z);
            macc8(acc, v3, *(unsigned long long*)&m3.z);
        }
        for (; j < n; j++) {
            int4 m0 = sM[j];
            uint4 v0 = xq[m0.x*64 + t];
            macc8(acc, v0, *(unsigned long long*)&m0.z);
        }
        __syncthreads();
    }

    uint4 hw;
    unsigned* hp = (unsigned*)&hw;
    #pragma unroll
    for (int q = 0; q < 4; q++) {
        float2 f = *(float2*)&acc[q];
        __half2 h = __floats2half2_rn(f.x, f.y);
        hp[q] = *(unsigned*)&h;
    }
    ((uint4*)(g_aggh + r*(ROWS*Hh) + dst*512))[t] = hw;
}

// ---------------- HMMA GEMM (smem-staged A) + LN + ReLU (+ fused out) -------
__global__ __launch_bounds__(256)
void gemm_mma_kernel(const float* __restrict__ ln_g, const float* __restrict__ ln_b,
                     const float* __restrict__ W_out, const float* __restrict__ b_out,
                     float* __restrict__ out, int layer, int final_layer)
{
    __shared__ __half sA[128][72];    // padded: conflict-free fragment LDS
    __shared__ uint2  sBs[4*8*32];    // B frags for current stream (8KB)
    __shared__ float  sLN[194];       // gamma | beta | W_out | b_out

    int tid = threadIdx.x;
    int wid = tid >> 5, lane = tid & 31;
    int qr = lane >> 2, qc = lane & 3;

    if (tid < 64)        sLN[tid] = ln_g[layer*64 + tid];
    else if (tid < 128)  sLN[tid] = ln_b[layer*64 + tid - 64];
    else if (tid < 192)  sLN[tid] = W_out[tid - 128];
    else if (tid == 192) sLN[192] = b_out[0];

    int m0 = blockIdx.x*128;
    int rl = wid*16 + qr;

    float c[8][4];
    #pragma unroll
    for (int nt = 0; nt < 8; nt++)
        #pragma unroll
        for (int i = 0; i < 4; i++) c[nt][i] = 0.f;

    for (int s = 0; s < 4; s++) {
        const uint4* Asrc = (const uint4*)(((s == 0) ? g_xh
                                : (g_aggh + (s-1)*(ROWS*Hh))) + m0*64);
        #pragma unroll
        for (int i = tid; i < 1024; i += 256) {
            int row = i >> 3, cq = i & 7;
            *(uint4*)&sA[row][cq*8] = Asrc[i];
        }
        const uint4* bsrc = (const uint4*)(g_bfrag + layer*4096 + s*1024);
        #pragma unroll
        for (int i = tid; i < 512; i += 256) ((uint4*)sBs)[i] = bsrc[i];
        __syncthreads();

        #pragma unroll
        for (int kti = 0; kti < 4; kti++) {
            int kh = kti*16 + qc*2;
            uint32_t a0 = *(const uint32_t*)&sA[rl][kh];
            uint32_t a1 = *(const uint32_t*)&sA[rl + 8][kh];
            uint32_t a2 = *(const uint32_t*)&sA[rl][kh + 8];
            uint32_t a3 = *(const uint32_t*)&sA[rl + 8][kh + 8];
            #pragma unroll
            for (int nt = 0; nt < 8; nt++) {
                uint2 b = sBs[(kti*8 + nt)*32 + lane];
                asm volatile(
                    "mma.sync.aligned.m16n8k16.row.col.f32.f16.f16.f32 "
                    "{%0,%1,%2,%3}, {%4,%5,%6,%7}, {%8,%9}, {%0,%1,%2,%3};"
                    : "+f"(c[nt][0]), "+f"(c[nt][1]), "+f"(c[nt][2]), "+f"(c[nt][3])
                    : "r"(a0), "r"(a1), "r"(a2), "r"(a3), "r"(b.x), "r"(b.y));
            }
        }
        __syncthreads();
    }

    #pragma unroll
    for (int h = 0; h < 2; h++) {
        int row = m0 + rl + h*8;
        float sum = 0.f, sq = 0.f;
        #pragma unroll
        for (int nt = 0; nt < 8; nt++) {
            float v0 = c[nt][2*h], v1 = c[nt][2*h + 1];
            sum += v0 + v1;
            sq   = fmaf(v0, v0, fmaf(v1, v1, sq));
        }
        sum += __shfl_xor_sync(0xffffffffu, sum, 1);
        sq  += __shfl_xor_sync(0xffffffffu, sq, 1);
        sum += __shfl_xor_sync(0xffffffffu, sum, 2);
        sq  += __shfl_xor_sync(0xffffffffu, sq, 2);
        float mu  = sum * (1.f/64.f);
        float var = sq  * (1.f/64.f) - mu*mu;
        float inv = rsqrtf(var + LN_EPS);
        if (!final_layer) {
            #pragma unroll
            for (int nt = 0; nt < 8; nt++) {
                int col = nt*8 + qc*2;
                float o0 = fmaxf(fmaf((c[nt][2*h]  -mu)*inv, sLN[col],   sLN[64+col]),   0.f);
                float o1 = fmaxf(fmaf((c[nt][2*h+1]-mu)*inv, sLN[col+1], sLN[64+col+1]), 0.f);
                __half2 hv = __floats2half2_rn(o0, o1);
                *(unsigned*)(g_xh + row*64 + col) = *(unsigned*)&hv;
            }
        } else {
            float dot = 0.f;
            #pragma unroll
            for (int nt = 0; nt < 8; nt++) {
                int col = nt*8 + qc*2;
                float o0 = fmaxf(fmaf((c[nt][2*h]  -mu)*inv, sLN[col],   sLN[64+col]),   0.f);
                float o1 = fmaxf(fmaf((c[nt][2*h+1]-mu)*inv, sLN[col+1], sLN[64+col+1]), 0.f);
                dot = fmaf(o0, sLN[128+col], fmaf(o1, sLN[128+col+1], dot));
            }
            dot += __shfl_xor_sync(0xffffffffu, dot, 1);
            dot += __shfl_xor_sync(0xffffffffu, dot, 2);
            if (qc == 0) {
                int b = row & 7, n = row >> 3;
                out[b*Nn + n] = dot + sLN[192];
            }
        }
    }
}

// ---------------- launch ----------------
extern "C" void kernel_launch(void* const* d_in, const int* in_sizes, int n_in,
                              void* d_out, int out_size)
{
    const float* ctl      = (const float*)d_in[0];
    const float* drug     = (const float*)d_in[1];
    const float* fp       = (const float*)d_in[2];
    const float* ew       = (const float*)d_in[3];
    const int*   cell_idx = (const int*)  d_in[4];
    const int*   ei       = (const int*)  d_in[5];
    const float* W_se     = (const float*)d_in[6];
    const float* b_se     = (const float*)d_in[7];
    const float* cell_emb = (const float*)d_in[8];
    const float* W_f1     = (const float*)d_in[9];
    const float* b_f1     = (const float*)d_in[10];
    const float* W_f2     = (const float*)d_in[11];
    const float* b_f2     = (const float*)d_in[12];
    const float* Wself    = (const float*)d_in[13];
    const float* Wrel     = (const float*)d_in[14];
    const float* ln_g     = (const float*)d_in[15];
    const float* ln_b     = (const float*)d_in[16];
    const float* W_out    = (const float*)d_in[17];
    const float* b_out    = (const float*)d_in[18];
    float* out = (float*)d_out;

    int npre = Rr*ESEG + Bn + (Ll*16*8*32 + 1023)/1024;   // 48
    pre_kernel<<<npre, 1024>>>(ei, fp, W_f1, b_f1, W_f2, b_f2, Wself, Wrel); // 1
    scan_kernel<<<Rr, 1024>>>();                                             // 2
    fillinit_kernel<<<FILLB + (ROWS*8 + 255)/256, 256>>>(
        ei, ew, ctl, drug, W_se, b_se, cell_emb, cell_idx);                  // 3

    for (int l = 0; l < Ll; l++) {
        gather_kernel<<<dim3(Nn, Rr), 64>>>();    // 4 on l==0  <- profiled
        gemm_mma_kernel<<<ROWS/128, 256>>>(ln_g, ln_b, W_out, b_out, out,
                                           l, (l == Ll-1) ? 1 : 0);
    }
}

// round 14
// speedup vs baseline: 3.4664x; 1.0190x over previous
#include <cuda_runtime.h>
#include <cuda_fp16.h>
#include <math.h>
#include <stdint.h>

#define Bn 8
#define Nn 10000
#define Hh 64
#define Ll 4
#define Rr 3
#define Ee 200000
#define FPn 2048
#define ROWS (Nn*Bn)            /* 80000 rows; row m = node*8 + b */
#define LN_EPS 1e-3f
#define FSEG 64                 /* hist/fill blocks per relation */
#define FCHUNK (Ee/FSEG)        /* 3125 */
#define FILLB (Rr*FSEG)         /* 192 */
#define GCH 128

// ---------------- device scratch ----------------
__device__ __half g_xh[ROWS*Hh];            // x (fp16) — single state buffer
__device__ __half g_aggh[Rr*ROWS*Hh];       // per-relation aggregation (fp16)
__device__ uint2  g_bfrag[Ll*16*8*32];      // B in exact mma-fragment order
__device__ float  g_film[Bn*2*Hh];
__device__ int    g_hist[Rr*Nn];            // degree hist (re-zeroed by scan)
__device__ int    g_rowptr[Rr*(Nn+1)];
__device__ int    g_cnt[Rr*Nn];             // atomic fill cursors
__device__ int2   g_epk[Rr*Ee];             // CSR packed (src, half2(w,w))

// ---------------- pre-kernel: hist(192, global atomics) + film(8) + prep_b(16)
__global__ __launch_bounds__(1024)
void pre_kernel(const int* __restrict__ ei,
                const float* __restrict__ fp,
                const float* __restrict__ W1, const float* __restrict__ b1,
                const float* __restrict__ W2, const float* __restrict__ b2,
                const float* __restrict__ Wself, const float* __restrict__ Wrel)
{
    __shared__ float part[1024];
    __shared__ float hid[64];
    int bk = blockIdx.x, t = threadIdx.x;

    if (bk < FILLB) {
        int r = bk / FSEG, seg = bk % FSEG;
        const int* dstp = ei + (r*2 + 1)*Ee + seg*FCHUNK;
        for (int e = t; e < FCHUNK; e += 1024)
            atomicAdd(&g_hist[r*Nn + dstp[e]], 1);
    } else if (bk < FILLB + Bn) {
        int b = bk - FILLB;
        int h = t >> 4, kc = t & 15;
        const float* fpb = fp + b*FPn;
        float a0 = 0.f, a1 = 0.f;
        int k0 = kc*128;
        for (int k = k0; k < k0 + 128; k += 2) {
            a0 = fmaf(fpb[k],   W1[k*Hh + h],     a0);
            a1 = fmaf(fpb[k+1], W1[(k+1)*Hh + h], a1);
        }
        part[t] = a0 + a1;
        __syncthreads();
        if (t < 64) {
            float a = b1[t];
            #pragma unroll
            for (int i = 0; i < 16; i++) a += part[t*16 + i];
            hid[t] = fmaxf(a, 0.f);
        }
        __syncthreads();
        if (t < 128) {
            int j = t;
            float a = b2[j];
            #pragma unroll
            for (int k = 0; k < Hh; k++) a += hid[k] * W2[k*128 + j];
            if (j < 64) g_film[b*128 + j] = 1.f + tanhf(a);
            else        g_film[b*128 + j] = a;
        }
    } else {
        int idx = (bk - FILLB - Bn)*1024 + t;
        if (idx < Ll*16*8*32) {
            int l    = idx >> 12;
            int kt   = (idx >> 8) & 15;
            int nt   = (idx >> 5) & 7;
            int lane = idx & 31;
            int s  = kt >> 2;
            int kb = (kt & 3)*16 + (lane & 3)*2;
            int n  = nt*8 + (lane >> 2);
            const float* W = (s == 0) ? (Wself + l*4096) : (Wrel + (l*Rr + s-1)*4096);
            __half2 lo = __floats2half2_rn(W[kb*64 + n],     W[(kb+1)*64 + n]);
            __half2 hi = __floats2half2_rn(W[(kb+8)*64 + n], W[(kb+9)*64 + n]);
            uint2 u;
            u.x = *(unsigned*)&lo;
            u.y = *(unsigned*)&hi;
            g_bfrag[idx] = u;
        }
    }
}

// ---------------- scan: rowptr + cursors; re-zeros g_hist -------------------
__global__ __launch_bounds__(1024)
void scan_kernel()   // grid = Rr x 1024
{
    __shared__ int wsum[32];
    int r = blockIdx.x, t = threadIdx.x;
    int lane = t & 31, warp = t >> 5;
    int carry = 0;
    if (t == 0) g_rowptr[r*(Nn+1)] = 0;
    for (int base = 0; base < Nn; base += 1024) {
        int idx = base + t;
        int v = (idx < Nn) ? g_hist[r*Nn + idx] : 0;
        int s = v;
        #pragma unroll
        for (int off = 1; off < 32; off <<= 1) {
            int nbr = __shfl_up_sync(0xffffffffu, s, off);
            if (lane >= off) s += nbr;
        }
        if (lane == 31) wsum[warp] = s;
        __syncthreads();
        if (warp == 0) {
            int w = wsum[lane];
            #pragma unroll
            for (int off = 1; off < 32; off <<= 1) {
                int nbr = __shfl_up_sync(0xffffffffu, w, off);
                if (lane >= off) w += nbr;
            }
            wsum[lane] = w;
        }
        __syncthreads();
        int tot = carry + (warp ? wsum[warp-1] : 0) + s;
        if (idx < Nn) {
            g_rowptr[r*(Nn+1) + idx + 1] = tot;
            g_cnt[r*Nn + idx]  = tot - v;
            g_hist[r*Nn + idx] = 0;
        }
        carry += wsum[31];
        __syncthreads();
    }
}

// ---------------- fused fill(192) + init(2500) ------------------------------
__global__ __launch_bounds__(256)
void fillinit_kernel(const int* __restrict__ ei, const float* __restrict__ ew,
                     const float* __restrict__ ctl, const float* __restrict__ drug,
                     const float* __restrict__ W_se, const float* __restrict__ b_se,
                     const float* __restrict__ cell_emb, const int* __restrict__ cell_idx)
{
    int bk = blockIdx.x, t = threadIdx.x;
    if (bk < FILLB) {
        int r = bk / FSEG, seg = bk % FSEG;
        const int* dstp = ei + (r*2 + 1)*Ee + seg*FCHUNK;
        const int* srcp = ei + (r*2 + 0)*Ee + seg*FCHUNK;
        const float* wp = ew + r*Ee + seg*FCHUNK;
        for (int e = t; e < FCHUNK; e += 256) {
            int dst = dstp[e];
            int pos = atomicAdd(&g_cnt[r*Nn + dst], 1);
            float wv = wp[e];
            __half2 wh = __floats2half2_rn(wv, wv);
            g_epk[r*Ee + pos] = make_int2(srcp[e], *(int*)&wh);
        }
        return;
    }
    // ---- init x: params staged in smem ----
    __shared__ float sp[1664];
    for (int i = t; i < 1664; i += 256) {
        float v;
        if (i < 64)        v = W_se[i];
        else if (i < 128)  v = b_se[i - 64];
        else if (i < 640) {
            int j = i - 128, b = j >> 6, h = j & 63;
            v = cell_emb[cell_idx[b]*Hh + h];
        } else if (i < 1152) {
            int j = i - 640, b = j >> 6, h = j & 63;
            v = g_film[b*128 + h];
        } else {
            int j = i - 1152, b = j >> 6, h = j & 63;
            v = g_film[b*128 + 64 + h];
        }
        sp[i] = v;
    }
    __syncthreads();

    int i = (bk - FILLB)*256 + t;
    if (i >= ROWS*8) return;
    int q = i & 7;
    int m = i >> 3;
    int b = m & 7;
    int n = m >> 3;
    float v1 = ctl[b*Nn + n], v2 = drug[b*Nn + n];
    const float4* w4  = (const float4*)&sp[q*8];
    const float4* bb4 = (const float4*)&sp[64 + q*8];
    const float4* ce4 = (const float4*)&sp[128 + b*64 + q*8];
    const float4* g4  = (const float4*)&sp[640 + b*64 + q*8];
    const float4* be4 = (const float4*)&sp[1152 + b*64 + q*8];
    uint4 outv;
    unsigned* op = (unsigned*)&outv;
    #pragma unroll
    for (int p = 0; p < 2; p++) {
        float4 w = w4[p], bb = bb4[p], ce = ce4[p], gg = g4[p], be = be4[p];
        float o[4];
        o[0] = fmaf(fmaxf(fmaf(v1, w.x, bb.x), 0.f) + fmaxf(fmaf(v2, w.x, bb.x), 0.f) + ce.x, gg.x, be.x);
        o[1] = fmaf(fmaxf(fmaf(v1, w.y, bb.y), 0.f) + fmaxf(fmaf(v2, w.y, bb.y), 0.f) + ce.y, gg.y, be.y);
        o[2] = fmaf(fmaxf(fmaf(v1, w.z, bb.z), 0.f) + fmaxf(fmaf(v2, w.z, bb.z), 0.f) + ce.z, gg.z, be.z);
        o[3] = fmaf(fmaxf(fmaf(v1, w.w, bb.w), 0.f) + fmaxf(fmaf(v2, w.w, bb.w), 0.f) + ce.w, gg.w, be.w);
        __half2 h0 = __floats2half2_rn(o[0], o[1]);
        __half2 h1 = __floats2half2_rn(o[2], o[3]);
        op[p*2]   = *(unsigned*)&h0;
        op[p*2+1] = *(unsigned*)&h1;
    }
    ((uint4*)g_xh)[i] = outv;
}

// ---------------- gather: HFMA2 8-edge windows, fp32 flush ------------------
__device__ __forceinline__ void hacc4(__half2* a, uint4 v, __half2 w2)
{
    a[0] = __hfma2(*(__half2*)&v.x, w2, a[0]);
    a[1] = __hfma2(*(__half2*)&v.y, w2, a[1]);
    a[2] = __hfma2(*(__half2*)&v.z, w2, a[2]);
    a[3] = __hfma2(*(__half2*)&v.w, w2, a[3]);
}
__device__ __forceinline__ void hflush(float* f, __half2* a, __half2 hz)
{
    #pragma unroll
    for (int q = 0; q < 4; q++) {
        float2 x = __half22float2(a[q]);
        f[2*q]   += x.x;
        f[2*q+1] += x.y;
        a[q] = hz;
    }
}

__global__ __launch_bounds__(64)
void gather_kernel()  // grid (Nn, Rr) x 64
{
    __shared__ int2 sM[GCH];
    int dst = blockIdx.x, r = blockIdx.y;
    int t = threadIdx.x;                       // owns 8 halfs of the 512-half row
    int start = g_rowptr[r*(Nn+1) + dst];
    int end   = g_rowptr[r*(Nn+1) + dst + 1];
    const uint4* __restrict__ xq = (const uint4*)g_xh;   // 64 uint4 per node row
    const int2* __restrict__ ep = g_epk + r*Ee;
    const __half2 hz = __float2half2_rn(0.f);
    float accf[8] = {0.f, 0.f, 0.f, 0.f, 0.f, 0.f, 0.f, 0.f};

    for (int base = start; base < end; base += GCH) {
        int n = min(GCH, end - base);
        if (t < n)       sM[t]      = ep[base + t];
        if (t + 64 < n)  sM[t + 64] = ep[base + t + 64];
        __syncthreads();
        int j = 0;
        for (; j + 8 <= n; j += 8) {
            __half2 a[4] = {hz, hz, hz, hz};
            int2 m0 = sM[j],   m1 = sM[j+1], m2 = sM[j+2], m3 = sM[j+3];
            int2 m4 = sM[j+4], m5 = sM[j+5], m6 = sM[j+6], m7 = sM[j+7];
            uint4 v0 = xq[m0.x*64 + t];
            uint4 v1 = xq[m1.x*64 + t];
            uint4 v2 = xq[m2.x*64 + t];
            uint4 v3 = xq[m3.x*64 + t];
            uint4 v4 = xq[m4.x*64 + t];
            uint4 v5 = xq[m5.x*64 + t];
            uint4 v6 = xq[m6.x*64 + t];
            uint4 v7 = xq[m7.x*64 + t];
            hacc4(a, v0, *(__half2*)&m0.y);
            hacc4(a, v1, *(__half2*)&m1.y);
            hacc4(a, v2, *(__half2*)&m2.y);
            hacc4(a, v3, *(__half2*)&m3.y);
            hacc4(a, v4, *(__half2*)&m4.y);
            hacc4(a, v5, *(__half2*)&m5.y);
            hacc4(a, v6, *(__half2*)&m6.y);
            hacc4(a, v7, *(__half2*)&m7.y);
            hflush(accf, a, hz);
        }
        if (j < n) {
            __half2 a[4] = {hz, hz, hz, hz};
            for (; j < n; j++) {
                int2 m0 = sM[j];
                uint4 v0 = xq[m0.x*64 + t];
                hacc4(a, v0, *(__half2*)&m0.y);
            }
            hflush(accf, a, hz);
        }
        __syncthreads();
    }

    uint4 hw;
    unsigned* hp = (unsigned*)&hw;
    #pragma unroll
    for (int q = 0; q < 4; q++) {
        __half2 h = __floats2half2_rn(accf[2*q], accf[2*q+1]);
        hp[q] = *(unsigned*)&h;
    }
    ((uint4*)(g_aggh + r*(ROWS*Hh) + dst*512))[t] = hw;
}

// ---------------- HMMA GEMM (smem-staged A) + LN + ReLU (+ fused out) -------
__global__ __launch_bounds__(256)
void gemm_mma_kernel(const float* __restrict__ ln_g, const float* __restrict__ ln_b,
                     const float* __restrict__ W_out, const float* __restrict__ b_out,
                     float* __restrict__ out, int layer, int final_layer)
{
    __shared__ __half sA[128][72];
    __shared__ uint2  sBs[4*8*32];
    __shared__ float  sLN[194];

    int tid = threadIdx.x;
    int wid = tid >> 5, lane = tid & 31;
    int qr = lane >> 2, qc = lane & 3;

    if (tid < 64)        sLN[tid] = ln_g[layer*64 + tid];
    else if (tid < 128)  sLN[tid] = ln_b[layer*64 + tid - 64];
    else if (tid < 192)  sLN[tid] = W_out[tid - 128];
    else if (tid == 192) sLN[192] = b_out[0];

    int m0 = blockIdx.x*128;
    int rl = wid*16 + qr;

    float c[8][4];
    #pragma unroll
    for (int nt = 0; nt < 8; nt++)
        #pragma unroll
        for (int i = 0; i < 4; i++) c[nt][i] = 0.f;

    for (int s = 0; s < 4; s++) {
        const uint4* Asrc = (const uint4*)(((s == 0) ? g_xh
                                : (g_aggh + (s-1)*(ROWS*Hh))) + m0*64);
        #pragma unroll
        for (int i = tid; i < 1024; i += 256) {
            int row = i >> 3, cq = i & 7;
            *(uint4*)&sA[row][cq*8] = Asrc[i];
        }
        const uint4* bsrc = (const uint4*)(g_bfrag + layer*4096 + s*1024);
        #pragma unroll
        for (int i = tid; i < 512; i += 256) ((uint4*)sBs)[i] = bsrc[i];
        __syncthreads();

        #pragma unroll
        for (int kti = 0; kti < 4; kti++) {
            int kh = kti*16 + qc*2;
            uint32_t a0 = *(const uint32_t*)&sA[rl][kh];
            uint32_t a1 = *(const uint32_t*)&sA[rl + 8][kh];
            uint32_t a2 = *(const uint32_t*)&sA[rl][kh + 8];
            uint32_t a3 = *(const uint32_t*)&sA[rl + 8][kh + 8];
            #pragma unroll
            for (int nt = 0; nt < 8; nt++) {
                uint2 b = sBs[(kti*8 + nt)*32 + lane];
                asm volatile(
                    "mma.sync.aligned.m16n8k16.row.col.f32.f16.f16.f32 "
                    "{%0,%1,%2,%3}, {%4,%5,%6,%7}, {%8,%9}, {%0,%1,%2,%3};"
                    : "+f"(c[nt][0]), "+f"(c[nt][1]), "+f"(c[nt][2]), "+f"(c[nt][3])
                    : "r"(a0), "r"(a1), "r"(a2), "r"(a3), "r"(b.x), "r"(b.y));
            }
        }
        __syncthreads();
    }

    #pragma unroll
    for (int h = 0; h < 2; h++) {
        int row = m0 + rl + h*8;
        float sum = 0.f, sq = 0.f;
        #pragma unroll
        for (int nt = 0; nt < 8; nt++) {
            float v0 = c[nt][2*h], v1 = c[nt][2*h + 1];
            sum += v0 + v1;
            sq   = fmaf(v0, v0, fmaf(v1, v1, sq));
        }
        sum += __shfl_xor_sync(0xffffffffu, sum, 1);
        sq  += __shfl_xor_sync(0xffffffffu, sq, 1);
        sum += __shfl_xor_sync(0xffffffffu, sum, 2);
        sq  += __shfl_xor_sync(0xffffffffu, sq, 2);
        float mu  = sum * (1.f/64.f);
        float var = sq  * (1.f/64.f) - mu*mu;
        float inv = rsqrtf(var + LN_EPS);
        if (!final_layer) {
            #pragma unroll
            for (int nt = 0; nt < 8; nt++) {
                int col = nt*8 + qc*2;
                float o0 = fmaxf(fmaf((c[nt][2*h]  -mu)*inv, sLN[col],   sLN[64+col]),   0.f);
                float o1 = fmaxf(fmaf((c[nt][2*h+1]-mu)*inv, sLN[col+1], sLN[64+col+1]), 0.f);
                __half2 hv = __floats2half2_rn(o0, o1);
                *(unsigned*)(g_xh + row*64 + col) = *(unsigned*)&hv;
            }
        } else {
            float dot = 0.f;
            #pragma unroll
            for (int nt = 0; nt < 8; nt++) {
                int col = nt*8 + qc*2;
                float o0 = fmaxf(fmaf((c[nt][2*h]  -mu)*inv, sLN[col],   sLN[64+col]),   0.f);
                float o1 = fmaxf(fmaf((c[nt][2*h+1]-mu)*inv, sLN[col+1], sLN[64+col+1]), 0.f);
                dot = fmaf(o0, sLN[128+col], fmaf(o1, sLN[128+col+1], dot));
            }
            dot += __shfl_xor_sync(0xffffffffu, dot, 1);
            dot += __shfl_xor_sync(0xffffffffu, dot, 2);
            if (qc == 0) {
                int b = row & 7, n = row >> 3;
                out[b*Nn + n] = dot + sLN[192];
            }
        }
    }
}

// ---------------- launch ----------------
extern "C" void kernel_launch(void* const* d_in, const int* in_sizes, int n_in,
                              void* d_out, int out_size)
{
    const float* ctl      = (const float*)d_in[0];
    const float* drug     = (const float*)d_in[1];
    const float* fp       = (const float*)d_in[2];
    const float* ew       = (const float*)d_in[3];
    const int*   cell_idx = (const int*)  d_in[4];
    const int*   ei       = (const int*)  d_in[5];
    const float* W_se     = (const float*)d_in[6];
    const float* b_se     = (const float*)d_in[7];
    const float* cell_emb = (const float*)d_in[8];
    const float* W_f1     = (const float*)d_in[9];
    const float* b_f1     = (const float*)d_in[10];
    const float* W_f2     = (const float*)d_in[11];
    const float* b_f2     = (const float*)d_in[12];
    const float* Wself    = (const float*)d_in[13];
    const float* Wrel     = (const float*)d_in[14];
    const float* ln_g     = (const float*)d_in[15];
    const float* ln_b     = (const float*)d_in[16];
    const float* W_out    = (const float*)d_in[17];
    const float* b_out    = (const float*)d_in[18];
    float* out = (float*)d_out;

    int npre = FILLB + Bn + (Ll*16*8*32 + 1023)/1024;   // 192 + 8 + 16 = 216
    pre_kernel<<<npre, 1024>>>(ei, fp, W_f1, b_f1, W_f2, b_f2, Wself, Wrel); // 1
    scan_kernel<<<Rr, 1024>>>();                                             // 2
    fillinit_kernel<<<FILLB + (ROWS*8 + 255)/256, 256>>>(
        ei, ew, ctl, drug, W_se, b_se, cell_emb, cell_idx);                  // 3

    for (int l = 0; l < Ll; l++) {
        gather_kernel<<<dim3(Nn, Rr), 64>>>();    // 4 on l==0  <- profiled
        gemm_mma_kernel<<<ROWS/128, 256>>>(ln_g, ln_b, W_out, b_out, out,
                                           l, (l == Ll-1) ? 1 : 0);
    }
}

// round 15
// speedup vs baseline: 3.6732x; 1.0597x over previous
#include <cuda_runtime.h>
#include <cuda_fp16.h>
#include <math.h>
#include <stdint.h>

#define Bn 8
#define Nn 10000
#define Hh 64
#define Ll 4
#define Rr 3
#define Ee 200000
#define FPn 2048
#define ROWS (Nn*Bn)            /* 80000 rows; row m = node*8 + b */
#define LN_EPS 1e-3f
#define FSEG 64                 /* hist/fill blocks per relation */
#define FCHUNK (Ee/FSEG)        /* 3125 */
#define FILLB (Rr*FSEG)         /* 192 */
#define GCH 128

#define GDC_WAIT() asm volatile("griddepcontrol.wait;" ::: "memory")
#define GDC_LAUNCH() asm volatile("griddepcontrol.launch_dependents;")

// ---------------- device scratch ----------------
__device__ __half g_xh[ROWS*Hh];            // x (fp16) — single state buffer
__device__ __half g_aggh[Rr*ROWS*Hh];       // per-relation aggregation (fp16)
__device__ uint2  g_bfrag[Ll*16*8*32];      // B in exact mma-fragment order
__device__ float  g_film[Bn*2*Hh];
__device__ int    g_hist[Rr*Nn];            // degree hist (re-zeroed by scan)
__device__ int    g_rowptr[Rr*(Nn+1)];
__device__ int    g_cnt[Rr*Nn];             // atomic fill cursors
__device__ int2   g_epk[Rr*Ee];             // CSR packed (src, half2(w,w))

// ---------------- pre-kernel: hist(192, global atomics) + film(8) + prep_b(16)
__global__ __launch_bounds__(1024)
void pre_kernel(const int* __restrict__ ei,
                const float* __restrict__ fp,
                const float* __restrict__ W1, const float* __restrict__ b1,
                const float* __restrict__ W2, const float* __restrict__ b2,
                const float* __restrict__ Wself, const float* __restrict__ Wrel)
{
    __shared__ float part[1024];
    __shared__ float hid[64];
    int bk = blockIdx.x, t = threadIdx.x;

    if (bk < FILLB) {
        int r = bk / FSEG, seg = bk % FSEG;
        const int* dstp = ei + (r*2 + 1)*Ee + seg*FCHUNK;
        for (int e = t; e < FCHUNK; e += 1024)
            atomicAdd(&g_hist[r*Nn + dstp[e]], 1);
    } else if (bk < FILLB + Bn) {
        int b = bk - FILLB;
        int h = t >> 4, kc = t & 15;
        const float* fpb = fp + b*FPn;
        float a0 = 0.f, a1 = 0.f;
        int k0 = kc*128;
        for (int k = k0; k < k0 + 128; k += 2) {
            a0 = fmaf(fpb[k],   W1[k*Hh + h],     a0);
            a1 = fmaf(fpb[k+1], W1[(k+1)*Hh + h], a1);
        }
        part[t] = a0 + a1;
        __syncthreads();
        if (t < 64) {
            float a = b1[t];
            #pragma unroll
            for (int i = 0; i < 16; i++) a += part[t*16 + i];
            hid[t] = fmaxf(a, 0.f);
        }
        __syncthreads();
        if (t < 128) {
            int j = t;
            float a = b2[j];
            #pragma unroll
            for (int k = 0; k < Hh; k++) a += hid[k] * W2[k*128 + j];
            if (j < 64) g_film[b*128 + j] = 1.f + tanhf(a);
            else        g_film[b*128 + j] = a;
        }
    } else {
        int idx = (bk - FILLB - Bn)*1024 + t;
        if (idx < Ll*16*8*32) {
            int l    = idx >> 12;
            int kt   = (idx >> 8) & 15;
            int nt   = (idx >> 5) & 7;
            int lane = idx & 31;
            int s  = kt >> 2;
            int kb = (kt & 3)*16 + (lane & 3)*2;
            int n  = nt*8 + (lane >> 2);
            const float* W = (s == 0) ? (Wself + l*4096) : (Wrel + (l*Rr + s-1)*4096);
            __half2 lo = __floats2half2_rn(W[kb*64 + n],     W[(kb+1)*64 + n]);
            __half2 hi = __floats2half2_rn(W[(kb+8)*64 + n], W[(kb+9)*64 + n]);
            uint2 u;
            u.x = *(unsigned*)&lo;
            u.y = *(unsigned*)&hi;
            g_bfrag[idx] = u;
        }
    }
    GDC_LAUNCH();
}

// ---------------- scan: rowptr + cursors; re-zeros g_hist -------------------
__global__ __launch_bounds__(1024)
void scan_kernel()   // grid = Rr x 1024
{
    __shared__ int wsum[32];
    int r = blockIdx.x, t = threadIdx.x;
    int lane = t & 31, warp = t >> 5;
    GDC_WAIT();                     // needs g_hist from pre
    int carry = 0;
    if (t == 0) g_rowptr[r*(Nn+1)] = 0;
    for (int base = 0; base < Nn; base += 1024) {
        int idx = base + t;
        int v = (idx < Nn) ? g_hist[r*Nn + idx] : 0;
        int s = v;
        #pragma unroll
        for (int off = 1; off < 32; off <<= 1) {
            int nbr = __shfl_up_sync(0xffffffffu, s, off);
            if (lane >= off) s += nbr;
        }
        if (lane == 31) wsum[warp] = s;
        __syncthreads();
        if (warp == 0) {
            int w = wsum[lane];
            #pragma unroll
            for (int off = 1; off < 32; off <<= 1) {
                int nbr = __shfl_up_sync(0xffffffffu, w, off);
                if (lane >= off) w += nbr;
            }
            wsum[lane] = w;
        }
        __syncthreads();
        int tot = carry + (warp ? wsum[warp-1] : 0) + s;
        if (idx < Nn) {
            g_rowptr[r*(Nn+1) + idx + 1] = tot;
            g_cnt[r*Nn + idx]  = tot - v;
            g_hist[r*Nn + idx] = 0;
        }
        carry += wsum[31];
        __syncthreads();
    }
    GDC_LAUNCH();
}

// ---------------- fused fill(192) + init(2500) ------------------------------
// fill blocks wait on scan (cursors); init blocks depend only on pre -> NO wait,
// they run fully overlapped with the 3-block scan.
__global__ __launch_bounds__(256)
void fillinit_kernel(const int* __restrict__ ei, const float* __restrict__ ew,
                     const float* __restrict__ ctl, const float* __restrict__ drug,
                     const float* __restrict__ W_se, const float* __restrict__ b_se,
                     const float* __restrict__ cell_emb, const int* __restrict__ cell_idx)
{
    int bk = blockIdx.x, t = threadIdx.x;
    if (bk < FILLB) {
        GDC_WAIT();                 // needs g_cnt cursors from scan
        int r = bk / FSEG, seg = bk % FSEG;
        const int* dstp = ei + (r*2 + 1)*Ee + seg*FCHUNK;
        const int* srcp = ei + (r*2 + 0)*Ee + seg*FCHUNK;
        const float* wp = ew + r*Ee + seg*FCHUNK;
        for (int e = t; e < FCHUNK; e += 256) {
            int dst = dstp[e];
            int pos = atomicAdd(&g_cnt[r*Nn + dst], 1);
            float wv = wp[e];
            __half2 wh = __floats2half2_rn(wv, wv);
            g_epk[r*Ee + pos] = make_int2(srcp[e], *(int*)&wh);
        }
        GDC_LAUNCH();
        return;
    }
    // ---- init x: reads only g_film (transitively complete) + inputs ----
    __shared__ float sp[1664];
    for (int i = t; i < 1664; i += 256) {
        float v;
        if (i < 64)        v = W_se[i];
        else if (i < 128)  v = b_se[i - 64];
        else if (i < 640) {
            int j = i - 128, b = j >> 6, h = j & 63;
            v = cell_emb[cell_idx[b]*Hh + h];
        } else if (i < 1152) {
            int j = i - 640, b = j >> 6, h = j & 63;
            v = g_film[b*128 + h];
        } else {
            int j = i - 1152, b = j >> 6, h = j & 63;
            v = g_film[b*128 + 64 + h];
        }
        sp[i] = v;
    }
    __syncthreads();

    int i = (bk - FILLB)*256 + t;
    if (i < ROWS*8) {
        int q = i & 7;
        int m = i >> 3;
        int b = m & 7;
        int n = m >> 3;
        float v1 = ctl[b*Nn + n], v2 = drug[b*Nn + n];
        const float4* w4  = (const float4*)&sp[q*8];
        const float4* bb4 = (const float4*)&sp[64 + q*8];
        const float4* ce4 = (const float4*)&sp[128 + b*64 + q*8];
        const float4* g4  = (const float4*)&sp[640 + b*64 + q*8];
        const float4* be4 = (const float4*)&sp[1152 + b*64 + q*8];
        uint4 outv;
        unsigned* op = (unsigned*)&outv;
        #pragma unroll
        for (int p = 0; p < 2; p++) {
            float4 w = w4[p], bb = bb4[p], ce = ce4[p], gg = g4[p], be = be4[p];
            float o[4];
            o[0] = fmaf(fmaxf(fmaf(v1, w.x, bb.x), 0.f) + fmaxf(fmaf(v2, w.x, bb.x), 0.f) + ce.x, gg.x, be.x);
            o[1] = fmaf(fmaxf(fmaf(v1, w.y, bb.y), 0.f) + fmaxf(fmaf(v2, w.y, bb.y), 0.f) + ce.y, gg.y, be.y);
            o[2] = fmaf(fmaxf(fmaf(v1, w.z, bb.z), 0.f) + fmaxf(fmaf(v2, w.z, bb.z), 0.f) + ce.z, gg.z, be.z);
            o[3] = fmaf(fmaxf(fmaf(v1, w.w, bb.w), 0.f) + fmaxf(fmaf(v2, w.w, bb.w), 0.f) + ce.w, gg.w, be.w);
            __half2 h0 = __floats2half2_rn(o[0], o[1]);
            __half2 h1 = __floats2half2_rn(o[2], o[3]);
            op[p*2]   = *(unsigned*)&h0;
            op[p*2+1] = *(unsigned*)&h1;
        }
        ((uint4*)g_xh)[i] = outv;
    }
    GDC_LAUNCH();
}

// ---------------- gather: HFMA2 8-edge windows, fp32 flush ------------------
__device__ __forceinline__ void hacc4(__half2* a, uint4 v, __half2 w2)
{
    a[0] = __hfma2(*(__half2*)&v.x, w2, a[0]);
    a[1] = __hfma2(*(__half2*)&v.y, w2, a[1]);
    a[2] = __hfma2(*(__half2*)&v.z, w2, a[2]);
    a[3] = __hfma2(*(__half2*)&v.w, w2, a[3]);
}
__device__ __forceinline__ void hflush(float* f, __half2* a, __half2 hz)
{
    #pragma unroll
    for (int q = 0; q < 4; q++) {
        float2 x = __half22float2(a[q]);
        f[2*q]   += x.x;
        f[2*q+1] += x.y;
        a[q] = hz;
    }
}

__global__ __launch_bounds__(64)
void gather_kernel()  // grid (Nn, Rr) x 64
{
    __shared__ int2 sM[GCH];
    int dst = blockIdx.x, r = blockIdx.y;
    int t = threadIdx.x;                       // owns 8 halfs of the 512-half row
    // rowptr comes from scan (>=2 kernels back; transitively complete) -> pre-wait
    int start = g_rowptr[r*(Nn+1) + dst];
    int end   = g_rowptr[r*(Nn+1) + dst + 1];
    GDC_WAIT();                                // x / meta from immediate predecessor
    const uint4* __restrict__ xq = (const uint4*)g_xh;   // 64 uint4 per node row
    const int2* __restrict__ ep = g_epk + r*Ee;
    const __half2 hz = __float2half2_rn(0.f);
    float accf[8] = {0.f, 0.f, 0.f, 0.f, 0.f, 0.f, 0.f, 0.f};

    for (int base = start; base < end; base += GCH) {
        int n = min(GCH, end - base);
        if (t < n)       sM[t]      = ep[base + t];
        if (t + 64 < n)  sM[t + 64] = ep[base + t + 64];
        __syncthreads();
        int j = 0;
        for (; j + 8 <= n; j += 8) {
            __half2 a[4] = {hz, hz, hz, hz};
            int2 m0 = sM[j],   m1 = sM[j+1], m2 = sM[j+2], m3 = sM[j+3];
            int2 m4 = sM[j+4], m5 = sM[j+5], m6 = sM[j+6], m7 = sM[j+7];
            uint4 v0 = xq[m0.x*64 + t];
            uint4 v1 = xq[m1.x*64 + t];
            uint4 v2 = xq[m2.x*64 + t];
            uint4 v3 = xq[m3.x*64 + t];
            uint4 v4 = xq[m4.x*64 + t];
            uint4 v5 = xq[m5.x*64 + t];
            uint4 v6 = xq[m6.x*64 + t];
            uint4 v7 = xq[m7.x*64 + t];
            hacc4(a, v0, *(__half2*)&m0.y);
            hacc4(a, v1, *(__half2*)&m1.y);
            hacc4(a, v2, *(__half2*)&m2.y);
            hacc4(a, v3, *(__half2*)&m3.y);
            hacc4(a, v4, *(__half2*)&m4.y);
            hacc4(a, v5, *(__half2*)&m5.y);
            hacc4(a, v6, *(__half2*)&m6.y);
            hacc4(a, v7, *(__half2*)&m7.y);
            hflush(accf, a, hz);
        }
        if (j < n) {
            __half2 a[4] = {hz, hz, hz, hz};
            for (; j < n; j++) {
                int2 m0 = sM[j];
                uint4 v0 = xq[m0.x*64 + t];
                hacc4(a, v0, *(__half2*)&m0.y);
            }
            hflush(accf, a, hz);
        }
        __syncthreads();
    }

    uint4 hw;
    unsigned* hp = (unsigned*)&hw;
    #pragma unroll
    for (int q = 0; q < 4; q++) {
        __half2 h = __floats2half2_rn(accf[2*q], accf[2*q+1]);
        hp[q] = *(unsigned*)&h;
    }
    ((uint4*)(g_aggh + r*(ROWS*Hh) + dst*512))[t] = hw;
    GDC_LAUNCH();
}

// ---------------- HMMA GEMM (smem-staged A) + LN + ReLU (+ fused out) -------
__global__ __launch_bounds__(256)
void gemm_mma_kernel(const float* __restrict__ ln_g, const float* __restrict__ ln_b,
                     const float* __restrict__ W_out, const float* __restrict__ b_out,
                     float* __restrict__ out, int layer, int final_layer)
{
    __shared__ __half sA[128][72];
    __shared__ uint2  sBs[4*8*32];
    __shared__ float  sLN[194];

    int tid = threadIdx.x;
    int wid = tid >> 5, lane = tid & 31;
    int qr = lane >> 2, qc = lane & 3;

    // LN/out params are kernel inputs -> stage before the dependency wait
    if (tid < 64)        sLN[tid] = ln_g[layer*64 + tid];
    else if (tid < 128)  sLN[tid] = ln_b[layer*64 + tid - 64];
    else if (tid < 192)  sLN[tid] = W_out[tid - 128];
    else if (tid == 192) sLN[192] = b_out[0];
    GDC_WAIT();                                // agg/x from gather

    int m0 = blockIdx.x*128;
    int rl = wid*16 + qr;

    float c[8][4];
    #pragma unroll
    for (int nt = 0; nt < 8; nt++)
        #pragma unroll
        for (int i = 0; i < 4; i++) c[nt][i] = 0.f;

    for (int s = 0; s < 4; s++) {
        const uint4* Asrc = (const uint4*)(((s == 0) ? g_xh
                                : (g_aggh + (s-1)*(ROWS*Hh))) + m0*64);
        #pragma unroll
        for (int i = tid; i < 1024; i += 256) {
            int row = i >> 3, cq = i & 7;
            *(uint4*)&sA[row][cq*8] = Asrc[i];
        }
        const uint4* bsrc = (const uint4*)(g_bfrag + layer*4096 + s*1024);
        #pragma unroll
        for (int i = tid; i < 512; i += 256) ((uint4*)sBs)[i] = bsrc[i];
        __syncthreads();

        #pragma unroll
        for (int kti = 0; kti < 4; kti++) {
            int kh = kti*16 + qc*2;
            uint32_t a0 = *(const uint32_t*)&sA[rl][kh];
            uint32_t a1 = *(const uint32_t*)&sA[rl + 8][kh];
            uint32_t a2 = *(const uint32_t*)&sA[rl][kh + 8];
            uint32_t a3 = *(const uint32_t*)&sA[rl + 8][kh + 8];
            #pragma unroll
            for (int nt = 0; nt < 8; nt++) {
                uint2 b = sBs[(kti*8 + nt)*32 + lane];
                asm volatile(
                    "mma.sync.aligned.m16n8k16.row.col.f32.f16.f16.f32 "
                    "{%0,%1,%2,%3}, {%4,%5,%6,%7}, {%8,%9}, {%0,%1,%2,%3};"
                    : "+f"(c[nt][0]), "+f"(c[nt][1]), "+f"(c[nt][2]), "+f"(c[nt][3])
                    : "r"(a0), "r"(a1), "r"(a2), "r"(a3), "r"(b.x), "r"(b.y));
            }
        }
        __syncthreads();
    }

    #pragma unroll
    for (int h = 0; h < 2; h++) {
        int row = m0 + rl + h*8;
        float sum = 0.f, sq = 0.f;
        #pragma unroll
        for (int nt = 0; nt < 8; nt++) {
            float v0 = c[nt][2*h], v1 = c[nt][2*h + 1];
            sum += v0 + v1;
            sq   = fmaf(v0, v0, fmaf(v1, v1, sq));
        }
        sum += __shfl_xor_sync(0xffffffffu, sum, 1);
        sq  += __shfl_xor_sync(0xffffffffu, sq, 1);
        sum += __shfl_xor_sync(0xffffffffu, sum, 2);
        sq  += __shfl_xor_sync(0xffffffffu, sq, 2);
        float mu  = sum * (1.f/64.f);
        float var = sq  * (1.f/64.f) - mu*mu;
        float inv = rsqrtf(var + LN_EPS);
        if (!final_layer) {
            #pragma unroll
            for (int nt = 0; nt < 8; nt++) {
                int col = nt*8 + qc*2;
                float o0 = fmaxf(fmaf((c[nt][2*h]  -mu)*inv, sLN[col],   sLN[64+col]),   0.f);
                float o1 = fmaxf(fmaf((c[nt][2*h+1]-mu)*inv, sLN[col+1], sLN[64+col+1]), 0.f);
                __half2 hv = __floats2half2_rn(o0, o1);
                *(unsigned*)(g_xh + row*64 + col) = *(unsigned*)&hv;
            }
        } else {
            float dot = 0.f;
            #pragma unroll
            for (int nt = 0; nt < 8; nt++) {
                int col = nt*8 + qc*2;
                float o0 = fmaxf(fmaf((c[nt][2*h]  -mu)*inv, sLN[col],   sLN[64+col]),   0.f);
                float o1 = fmaxf(fmaf((c[nt][2*h+1]-mu)*inv, sLN[col+1], sLN[64+col+1]), 0.f);
                dot = fmaf(o0, sLN[128+col], fmaf(o1, sLN[128+col+1], dot));
            }
            dot += __shfl_xor_sync(0xffffffffu, dot, 1);
            dot += __shfl_xor_sync(0xffffffffu, dot, 2);
            if (qc == 0) {
                int b = row & 7, n = row >> 3;
                out[b*Nn + n] = dot + sLN[192];
            }
        }
    }
    GDC_LAUNCH();
}

// ---------------- PDL launch helper ----------------
static void launch_pdl(const void* fn, dim3 grid, dim3 block, void** args)
{
    cudaLaunchConfig_t cfg = {};
    cfg.gridDim = grid;
    cfg.blockDim = block;
    cfg.dynamicSmemBytes = 0;
    cfg.stream = 0;
    cudaLaunchAttribute at[1];
    at[0].id = cudaLaunchAttributeProgrammaticStreamSerialization;
    at[0].val.programmaticStreamSerializationAllowed = 1;
    cfg.attrs = at;
    cfg.numAttrs = 1;
    cudaLaunchKernelExC(&cfg, fn, args);
}

// ---------------- launch ----------------
extern "C" void kernel_launch(void* const* d_in, const int* in_sizes, int n_in,
                              void* d_out, int out_size)
{
    const float* ctl      = (const float*)d_in[0];
    const float* drug     = (const float*)d_in[1];
    const float* fp       = (const float*)d_in[2];
    const float* ew       = (const float*)d_in[3];
    const int*   cell_idx = (const int*)  d_in[4];
    const int*   ei       = (const int*)  d_in[5];
    const float* W_se     = (const float*)d_in[6];
    const float* b_se     = (const float*)d_in[7];
    const float* cell_emb = (const float*)d_in[8];
    const float* W_f1     = (const float*)d_in[9];
    const float* b_f1     = (const float*)d_in[10];
    const float* W_f2     = (const float*)d_in[11];
    const float* b_f2     = (const float*)d_in[12];
    const float* Wself    = (const float*)d_in[13];
    const float* Wrel     = (const float*)d_in[14];
    const float* ln_g     = (const float*)d_in[15];
    const float* ln_b     = (const float*)d_in[16];
    const float* W_out    = (const float*)d_in[17];
    const float* b_out    = (const float*)d_in[18];
    float* out = (float*)d_out;

    int npre = FILLB + Bn + (Ll*16*8*32 + 1023)/1024;   // 216
    {
        void* a[] = {(void*)&ei, (void*)&fp, (void*)&W_f1, (void*)&b_f1,
                     (void*)&W_f2, (void*)&b_f2, (void*)&Wself, (void*)&Wrel};
        launch_pdl((const void*)pre_kernel, dim3(npre), dim3(1024), a);      // 1
    }
    {
        void* a[] = {nullptr};
        launch_pdl((const void*)scan_kernel, dim3(Rr), dim3(1024), a);       // 2
    }
    {
        void* a[] = {(void*)&ei, (void*)&ew, (void*)&ctl, (void*)&drug,
                     (void*)&W_se, (void*)&b_se, (void*)&cell_emb, (void*)&cell_idx};
        launch_pdl((const void*)fillinit_kernel,
                   dim3(FILLB + (ROWS*8 + 255)/256), dim3(256), a);          // 3
    }

    int layers[Ll]  = {0, 1, 2, 3};
    int finals[Ll]  = {0, 0, 0, 1};
    for (int l = 0; l < Ll; l++) {
        {
            void* a[] = {nullptr};
            launch_pdl((const void*)gather_kernel, dim3(Nn, Rr), dim3(64), a);
        }
        {
            void* a[] = {(void*)&ln_g, (void*)&ln_b, (void*)&W_out, (void*)&b_out,
                         (void*)&out, (void*)&layers[l], (void*)&finals[l]};
            launch_pdl((const void*)gemm_mma_kernel, dim3(ROWS/128), dim3(256), a);
        }
    }
}